// round 1
// baseline (speedup 1.0000x reference)
#include <cuda_runtime.h>
#include <math.h>

// Problem constants
constexpr int B_ = 4, T_ = 2048, C_ = 1024, H_ = 16, HS_ = 64;
constexpr int BT = B_ * T_;            // 8192 rows
constexpr int C3 = 3 * C_;             // 3072
constexpr float EPS = 1e-5f;

// Output layout (concatenated float32):
// [x: BT*C][k_quant: BT*C][k_scale: 1][v_quant: BT*C][v_scale: 1]
constexpr int OFF_X  = 0;
constexpr int OFF_KQ = BT * C_;                 // 8388608
constexpr int OFF_KS = OFF_KQ + BT * C_;        // 16777216
constexpr int OFF_VQ = OFF_KS + 1;              // 16777217
constexpr int OFF_VS = OFF_VQ + BT * C_;        // 25165825

// ---------------- scratch (device globals; no allocation allowed) -----------
__device__ float g_h  [BT * C_];       // LN output (reused for ln1 and ln2)
__device__ float g_qkv[BT * C3];       // QKV
__device__ float g_y  [BT * C_];       // attention output
__device__ float g_x1 [BT * C_];       // residual after attention
__device__ float g_fc [BT * 4 * C_];   // MLP hidden
__device__ unsigned g_absmax[2];       // k, v absmax (float bits)

// ---------------- LayerNorm ----------------
__global__ __launch_bounds__(256) void ln_kernel(const float* __restrict__ in,
                                                 const float* __restrict__ w,
                                                 const float* __restrict__ bvec,
                                                 float* __restrict__ out) {
    int row = blockIdx.x;
    const float* r = in + (size_t)row * C_;
    int tid = threadIdx.x;
    float v[4];
    float s = 0.f, ss = 0.f;
#pragma unroll
    for (int i = 0; i < 4; i++) {
        v[i] = r[tid + i * 256];
        s += v[i];
        ss += v[i] * v[i];
    }
#pragma unroll
    for (int o = 16; o; o >>= 1) {
        s  += __shfl_xor_sync(0xffffffffu, s, o);
        ss += __shfl_xor_sync(0xffffffffu, ss, o);
    }
    __shared__ float rs_[8], rss_[8];
    __shared__ float s_mean, s_rstd;
    int warp = tid >> 5, lane = tid & 31;
    if (lane == 0) { rs_[warp] = s; rss_[warp] = ss; }
    __syncthreads();
    if (tid == 0) {
        float ts = 0.f, tss = 0.f;
#pragma unroll
        for (int i = 0; i < 8; i++) { ts += rs_[i]; tss += rss_[i]; }
        float mean = ts * (1.0f / C_);
        float var = tss * (1.0f / C_) - mean * mean;
        s_mean = mean;
        s_rstd = rsqrtf(var + EPS);
    }
    __syncthreads();
    float mean = s_mean, rstd = s_rstd;
    float* o = out + (size_t)row * C_;
#pragma unroll
    for (int i = 0; i < 4; i++) {
        int c = tid + i * 256;
        o[c] = (v[i] - mean) * rstd * w[c] + bvec[c];
    }
}

// ---------------- SGEMM 128x128x16, 256 threads, 8x8 microtile --------------
// EPI: 0 = bias, 1 = bias+gelu(exact), 2 = bias+residual
template <int EPI>
__global__ __launch_bounds__(256) void sgemm_k(const float* __restrict__ A,
                                               const float* __restrict__ Bm,
                                               const float* __restrict__ bias,
                                               const float* __restrict__ R,
                                               float* __restrict__ Cm,
                                               int M, int N, int K) {
    __shared__ float As[16][128];
    __shared__ float Bs[16][128];

    int tid = threadIdx.x;
    int ty = tid >> 4, tx = tid & 15;
    int rowC = blockIdx.y * 128, colC = blockIdx.x * 128;

    float acc[8][8];
#pragma unroll
    for (int i = 0; i < 8; i++)
#pragma unroll
        for (int j = 0; j < 8; j++) acc[i][j] = 0.f;

    for (int k0 = 0; k0 < K; k0 += 16) {
        // A tile: 128 rows x 16 cols (store transposed into As[k][m])
#pragma unroll
        for (int i = 0; i < 2; i++) {
            int idx = tid * 2 + i;           // 0..511
            int r = idx >> 2, c4 = idx & 3;  // r:0..127 c4:0..3
            float4 a = *(const float4*)(A + (size_t)(rowC + r) * K + k0 + c4 * 4);
            As[c4 * 4 + 0][r] = a.x;
            As[c4 * 4 + 1][r] = a.y;
            As[c4 * 4 + 2][r] = a.z;
            As[c4 * 4 + 3][r] = a.w;
        }
        // B tile: 16 rows x 128 cols
#pragma unroll
        for (int i = 0; i < 2; i++) {
            int idx = tid * 2 + i;             // 0..511
            int r = idx >> 5, c4 = idx & 31;   // r:0..15 c4:0..31
            *(float4*)(&Bs[r][c4 * 4]) =
                *(const float4*)(Bm + (size_t)(k0 + r) * N + colC + c4 * 4);
        }
        __syncthreads();
#pragma unroll
        for (int kk = 0; kk < 16; kk++) {
            float a[8], b[8];
#pragma unroll
            for (int i = 0; i < 8; i++) a[i] = As[kk][ty * 8 + i];
#pragma unroll
            for (int j = 0; j < 8; j++) b[j] = Bs[kk][tx * 8 + j];
#pragma unroll
            for (int i = 0; i < 8; i++)
#pragma unroll
                for (int j = 0; j < 8; j++) acc[i][j] += a[i] * b[j];
        }
        __syncthreads();
    }

#pragma unroll
    for (int i = 0; i < 8; i++) {
        int r = rowC + ty * 8 + i;
#pragma unroll
        for (int j = 0; j < 8; j++) {
            int c = colC + tx * 8 + j;
            float v = acc[i][j] + bias[c];
            if (EPI == 1) v = 0.5f * v * (1.f + erff(v * 0.70710678118654752f));
            if (EPI == 2) v += R[(size_t)r * N + c];
            Cm[(size_t)r * N + c] = v;
        }
    }
}

// ---------------- Flash attention (causal, fp32) -----------------------------
// Block: 256 threads handle one 64-query tile for one (b, head).
// Shared tiles 64x64 padded to 65, dynamic shared 4*64*65*4 = 66560 B.
constexpr int SMEM_FLASH = 4 * 64 * 65 * 4;

__global__ __launch_bounds__(256) void flash_kernel() {
    extern __shared__ float sh[];
    float* qs = sh;             // [64][65]
    float* ks = sh + 64 * 65;
    float* vs = sh + 2 * 64 * 65;
    float* ps = sh + 3 * 64 * 65;

    int qt = blockIdx.x;        // 0..31
    int bh = blockIdx.y;        // 0..63
    int b = bh >> 4, h = bh & 15;
    const float* base = g_qkv + (size_t)b * T_ * C3 + h * HS_;

    int tid = threadIdx.x;
    int ty = tid >> 4, tx = tid & 15;

    // load q tile
#pragma unroll
    for (int i = 0; i < 4; i++) {
        int idx = tid + 256 * i;            // 0..1023
        int r = idx >> 4, c4 = idx & 15;    // r:0..63 c4:0..15
        float4 v4 = *(const float4*)(base + (size_t)(qt * 64 + r) * C3 + c4 * 4);
        float* d = qs + r * 65 + c4 * 4;
        d[0] = v4.x; d[1] = v4.y; d[2] = v4.z; d[3] = v4.w;
    }

    float m[4], l[4], acc[4][4];
#pragma unroll
    for (int i = 0; i < 4; i++) {
        m[i] = -1e30f;
        l[i] = 0.f;
#pragma unroll
        for (int j = 0; j < 4; j++) acc[i][j] = 0.f;
    }
    __syncthreads();

    for (int kt = 0; kt <= qt; kt++) {
        // load k,v tiles
#pragma unroll
        for (int i = 0; i < 4; i++) {
            int idx = tid + 256 * i;
            int r = idx >> 4, c4 = idx & 15;
            const float* kp = base + C_ + (size_t)(kt * 64 + r) * C3 + c4 * 4;
            float4 k4 = *(const float4*)kp;
            float* dk = ks + r * 65 + c4 * 4;
            dk[0] = k4.x; dk[1] = k4.y; dk[2] = k4.z; dk[3] = k4.w;
            float4 v4 = *(const float4*)(kp + C_);
            float* dv = vs + r * 65 + c4 * 4;
            dv[0] = v4.x; dv[1] = v4.y; dv[2] = v4.z; dv[3] = v4.w;
        }
        __syncthreads();

        // S = q @ k^T * scale
        float s[4][4];
#pragma unroll
        for (int i = 0; i < 4; i++)
#pragma unroll
            for (int j = 0; j < 4; j++) s[i][j] = 0.f;
        for (int d = 0; d < 64; d++) {
            float a[4], bb[4];
#pragma unroll
            for (int i = 0; i < 4; i++) a[i] = qs[(ty * 4 + i) * 65 + d];
#pragma unroll
            for (int j = 0; j < 4; j++) bb[j] = ks[(tx * 4 + j) * 65 + d];
#pragma unroll
            for (int i = 0; i < 4; i++)
#pragma unroll
                for (int j = 0; j < 4; j++) s[i][j] += a[i] * bb[j];
        }
        bool diag = (kt == qt);
#pragma unroll
        for (int i = 0; i < 4; i++)
#pragma unroll
            for (int j = 0; j < 4; j++) {
                s[i][j] *= 0.125f;  // 1/sqrt(64)
                if (diag && (tx * 4 + j) > (ty * 4 + i)) s[i][j] = -1e30f;
            }

        // online softmax
        float alpha[4];
#pragma unroll
        for (int i = 0; i < 4; i++) {
            float mx = s[i][0];
#pragma unroll
            for (int j = 1; j < 4; j++) mx = fmaxf(mx, s[i][j]);
#pragma unroll
            for (int o = 1; o < 16; o <<= 1)
                mx = fmaxf(mx, __shfl_xor_sync(0xffffffffu, mx, o));
            float mnew = fmaxf(m[i], mx);
            alpha[i] = __expf(m[i] - mnew);
            float sm = 0.f;
#pragma unroll
            for (int j = 0; j < 4; j++) {
                s[i][j] = __expf(s[i][j] - mnew);
                sm += s[i][j];
            }
#pragma unroll
            for (int o = 1; o < 16; o <<= 1)
                sm += __shfl_xor_sync(0xffffffffu, sm, o);
            l[i] = l[i] * alpha[i] + sm;
            m[i] = mnew;
        }

        // P to shared
#pragma unroll
        for (int i = 0; i < 4; i++)
#pragma unroll
            for (int j = 0; j < 4; j++)
                ps[(ty * 4 + i) * 65 + tx * 4 + j] = s[i][j];
        __syncthreads();

        // acc = acc*alpha + P @ V
#pragma unroll
        for (int i = 0; i < 4; i++)
#pragma unroll
            for (int j = 0; j < 4; j++) acc[i][j] *= alpha[i];
        for (int kk = 0; kk < 64; kk++) {
            float p[4], vv[4];
#pragma unroll
            for (int i = 0; i < 4; i++) p[i] = ps[(ty * 4 + i) * 65 + kk];
#pragma unroll
            for (int j = 0; j < 4; j++) vv[j] = vs[kk * 65 + tx * 4 + j];
#pragma unroll
            for (int i = 0; i < 4; i++)
#pragma unroll
                for (int j = 0; j < 4; j++) acc[i][j] += p[i] * vv[j];
        }
        __syncthreads();
    }

    // write y (B,T,C layout)
#pragma unroll
    for (int i = 0; i < 4; i++) {
        float inv = 1.f / l[i];
        int t = qt * 64 + ty * 4 + i;
        float* o = g_y + (size_t)(b * T_ + t) * C_ + h * HS_ + tx * 4;
#pragma unroll
        for (int j = 0; j < 4; j++) o[j] = acc[i][j] * inv;
    }
}

// ---------------- KV quantization --------------------------------------------
__global__ void init_absmax_kernel() {
    g_absmax[0] = 0u;
    g_absmax[1] = 0u;
}

__global__ __launch_bounds__(256) void absmax_kernel() {
    float mk = 0.f, mv = 0.f;
    int N = BT * C_;
    for (int i = blockIdx.x * blockDim.x + threadIdx.x; i < N;
         i += gridDim.x * blockDim.x) {
        int bt = i >> 10;       // /C_
        int c = i & (C_ - 1);
        const float* p = g_qkv + (size_t)bt * C3;
        mk = fmaxf(mk, fabsf(p[C_ + c]));
        mv = fmaxf(mv, fabsf(p[2 * C_ + c]));
    }
#pragma unroll
    for (int o = 16; o; o >>= 1) {
        mk = fmaxf(mk, __shfl_xor_sync(0xffffffffu, mk, o));
        mv = fmaxf(mv, __shfl_xor_sync(0xffffffffu, mv, o));
    }
    __shared__ float sk_[8], sv_[8];
    int warp = threadIdx.x >> 5, lane = threadIdx.x & 31;
    if (lane == 0) { sk_[warp] = mk; sv_[warp] = mv; }
    __syncthreads();
    if (threadIdx.x == 0) {
        float tk = 0.f, tv = 0.f;
#pragma unroll
        for (int i = 0; i < 8; i++) {
            tk = fmaxf(tk, sk_[i]);
            tv = fmaxf(tv, sv_[i]);
        }
        atomicMax(&g_absmax[0], __float_as_uint(tk));
        atomicMax(&g_absmax[1], __float_as_uint(tv));
    }
}

__global__ __launch_bounds__(256) void quant_kernel(float* __restrict__ out) {
    float ak = __uint_as_float(g_absmax[0]);
    float av = __uint_as_float(g_absmax[1]);
    float sk = ak > 0.f ? ak * (1.f / 127.f) : 1.f;
    float sv = av > 0.f ? av * (1.f / 127.f) : 1.f;
    float rk = 1.f / sk, rv = 1.f / sv;
    int N = BT * C_;  // elements per tensor in (B,H,T,HS) layout
    for (int idx = blockIdx.x * blockDim.x + threadIdx.x; idx < N;
         idx += gridDim.x * blockDim.x) {
        int d = idx & 63;
        int t = (idx >> 6) & 2047;
        int h = (idx >> 17) & 15;
        int b = idx >> 21;
        const float* src = g_qkv + (size_t)(b * T_ + t) * C3 + h * HS_ + d;
        float kq = fminf(fmaxf(rintf(src[C_] * rk), -127.f), 127.f);
        float vq = fminf(fmaxf(rintf(src[2 * C_] * rv), -127.f), 127.f);
        out[OFF_KQ + idx] = kq;
        out[OFF_VQ + idx] = vq;
    }
    if (blockIdx.x == 0 && threadIdx.x == 0) {
        out[OFF_KS] = sk;
        out[OFF_VS] = sv;
    }
}

// ---------------- launch ------------------------------------------------------
extern "C" void kernel_launch(void* const* d_in, const int* in_sizes, int n_in,
                              void* d_out, int out_size) {
    const float* x     = (const float*)d_in[0];
    const float* ln1_w = (const float*)d_in[1];
    const float* ln1_b = (const float*)d_in[2];
    const float* W_qkv = (const float*)d_in[3];
    const float* b_qkv = (const float*)d_in[4];
    const float* W_o   = (const float*)d_in[5];
    const float* b_o   = (const float*)d_in[6];
    const float* ln2_w = (const float*)d_in[7];
    const float* ln2_b = (const float*)d_in[8];
    const float* W_fc  = (const float*)d_in[9];
    const float* b_fc  = (const float*)d_in[10];
    const float* W_pr  = (const float*)d_in[11];
    const float* b_pr  = (const float*)d_in[12];
    float* out = (float*)d_out;

    float *h, *qkv, *y, *x1, *fc;
    cudaGetSymbolAddress((void**)&h, g_h);
    cudaGetSymbolAddress((void**)&qkv, g_qkv);
    cudaGetSymbolAddress((void**)&y, g_y);
    cudaGetSymbolAddress((void**)&x1, g_x1);
    cudaGetSymbolAddress((void**)&fc, g_fc);

    cudaFuncSetAttribute(flash_kernel,
                         cudaFuncAttributeMaxDynamicSharedMemorySize, SMEM_FLASH);

    // 1. LN1
    ln_kernel<<<BT, 256>>>(x, ln1_w, ln1_b, h);
    // 2. QKV GEMM: (8192,1024) @ (1024,3072)
    sgemm_k<0><<<dim3(C3 / 128, BT / 128), 256>>>(h, W_qkv, b_qkv, nullptr, qkv,
                                                  BT, C3, C_);
    // 3. Causal flash attention
    flash_kernel<<<dim3(T_ / 64, B_ * H_), 256, SMEM_FLASH>>>();
    // 4. Output proj + residual: x1 = y @ W_o + b_o + x
    sgemm_k<2><<<dim3(C_ / 128, BT / 128), 256>>>(y, W_o, b_o, x, x1,
                                                  BT, C_, C_);
    // 5. LN2
    ln_kernel<<<BT, 256>>>(x1, ln2_w, ln2_b, h);
    // 6. FC + GELU: (8192,1024) @ (1024,4096)
    sgemm_k<1><<<dim3(4 * C_ / 128, BT / 128), 256>>>(h, W_fc, b_fc, nullptr, fc,
                                                      BT, 4 * C_, C_);
    // 7. Proj + residual -> final x (directly into out)
    sgemm_k<2><<<dim3(C_ / 128, BT / 128), 256>>>(fc, W_pr, b_pr, x1,
                                                  out + OFF_X, BT, C_, 4 * C_);
    // 8-10. KV int8 quantization
    init_absmax_kernel<<<1, 1>>>();
    absmax_kernel<<<2048, 256>>>();
    quant_kernel<<<4096, 256>>>(out);
}

// round 3
// speedup vs baseline: 2.1971x; 2.1971x over previous
#include <cuda_runtime.h>
#include <cuda_bf16.h>
#include <cstdint>
#include <math.h>

// Problem constants
constexpr int B_ = 4, T_ = 2048, C_ = 1024, H_ = 16, HS_ = 64;
constexpr int BT = B_ * T_;            // 8192 rows
constexpr int C3 = 3 * C_;             // 3072
constexpr float EPS = 1e-5f;

// Output layout (concatenated float32):
constexpr int OFF_X  = 0;
constexpr int OFF_KQ = BT * C_;
constexpr int OFF_KS = OFF_KQ + BT * C_;
constexpr int OFF_VQ = OFF_KS + 1;
constexpr int OFF_VS = OFF_VQ + BT * C_;

// ---------------- scratch (device globals) -----------------------------------
__device__ float g_qkv[BT * C3];
__device__ float g_x1 [BT * C_];
__device__ __nv_bfloat16 g_a_hi [BT * C_],     g_a_lo [BT * C_];
__device__ __nv_bfloat16 g_y_hi [BT * C_],     g_y_lo [BT * C_];
__device__ __nv_bfloat16 g_fc_hi[BT * 4 * C_], g_fc_lo[BT * 4 * C_];
__device__ __nv_bfloat16 g_wqkv_hi[C3 * C_],    g_wqkv_lo[C3 * C_];
__device__ __nv_bfloat16 g_wo_hi  [C_ * C_],    g_wo_lo  [C_ * C_];
__device__ __nv_bfloat16 g_wfc_hi [4 * C_ * C_],g_wfc_lo [4 * C_ * C_];
__device__ __nv_bfloat16 g_wpr_hi [C_ * 4 * C_],g_wpr_lo [C_ * 4 * C_];
__device__ unsigned g_absmax[2];

// ---------------- helpers -------------------------------------------------
__device__ __forceinline__ uint32_t smem_u32(const void* p) {
    return (uint32_t)__cvta_generic_to_shared(p);
}
__device__ __forceinline__ void cp_async16(uint32_t dst, const void* src) {
    asm volatile("cp.async.cg.shared.global [%0], [%1], 16;"
                 :: "r"(dst), "l"(src) : "memory");
}
__device__ __forceinline__ void cp_commit() {
    asm volatile("cp.async.commit_group;" ::: "memory");
}
__device__ __forceinline__ void ldmatrix_x4(uint32_t* r, uint32_t addr) {
    asm volatile("ldmatrix.sync.aligned.m8n8.x4.shared.b16 {%0,%1,%2,%3}, [%4];"
                 : "=r"(r[0]), "=r"(r[1]), "=r"(r[2]), "=r"(r[3]) : "r"(addr));
}
__device__ __forceinline__ void mma_bf16(float* d, const uint32_t* a, const uint32_t* b) {
    asm volatile("mma.sync.aligned.m16n8k16.row.col.f32.bf16.bf16.f32 "
                 "{%0,%1,%2,%3},{%4,%5,%6,%7},{%8,%9},{%0,%1,%2,%3};"
                 : "+f"(d[0]), "+f"(d[1]), "+f"(d[2]), "+f"(d[3])
                 : "r"(a[0]), "r"(a[1]), "r"(a[2]), "r"(a[3]),
                   "r"(b[0]), "r"(b[1]));
}
__device__ __forceinline__ void split_bf16(float v, __nv_bfloat16& hi, __nv_bfloat16& lo) {
    hi = __float2bfloat16(v);
    lo = __float2bfloat16(v - __bfloat162float(hi));
}

// ---------------- HMMA GEMM: C[M,N] = A[M,K] @ W[K,N], B = W^T [N,K] ---------
// CTA tile 128x128, K-chunk 64 bf16, 8 warps (4m x 2n), warp tile 32x64.
// bf16x3 split: hi*hi + hi*lo + lo*hi.
// SMEM per stage: Ah|Al|Bh|Bl each 16KB = 64KB; 2 stages = 128KB.
// EPI: 0 = bias -> f32; 1 = bias+gelu -> bf16 hi/lo; 2 = bias+residual -> f32
constexpr int SMEM_GEMM = 131072;

template <int EPI>
__global__ __launch_bounds__(256, 1)
void mma_gemm(const __nv_bfloat16* __restrict__ Ah, const __nv_bfloat16* __restrict__ Al,
              const __nv_bfloat16* __restrict__ Bh, const __nv_bfloat16* __restrict__ Bl,
              const float* __restrict__ bias, const float* __restrict__ R,
              float* __restrict__ Cf,
              __nv_bfloat16* __restrict__ Ch, __nv_bfloat16* __restrict__ Cl,
              int M, int N, int K) {
    extern __shared__ __align__(1024) char smx[];
    const uint32_t sbase = smem_u32(smx);
    const int tid = threadIdx.x;
    const int wid = tid >> 5, lane = tid & 31;
    const int warp_m = wid & 3, warp_n = wid >> 2;
    const int rowC = blockIdx.y * 128, colC = blockIdx.x * 128;
    const int NC = K >> 6;

    float acc[2][8][4];
#pragma unroll
    for (int i = 0; i < 2; i++)
#pragma unroll
        for (int j = 0; j < 8; j++)
#pragma unroll
            for (int q = 0; q < 4; q++) acc[i][j][q] = 0.f;

    // per-thread cp.async indices: u = tid + 256*i -> row = u>>3 (0..127), seg = u&7
    const int ld_r = tid >> 3;          // base row for i=0 (0..31)
    const int ld_seg = tid & 7;

    // ---- issue chunk c into stage c&1 ----
    auto issue = [&](int c) {
        const uint32_t sb = sbase + (uint32_t)(c & 1) * 65536u;
        const int k0 = c << 6;
#pragma unroll
        for (int i = 0; i < 4; i++) {
            int r = ld_r + i * 32;
            uint32_t so = (uint32_t)(r * 128 + ((ld_seg * 16) ^ ((r & 7) * 16)));
            size_t goA = (size_t)(rowC + r) * K + k0 + ld_seg * 8;
            size_t goB = (size_t)(colC + r) * K + k0 + ld_seg * 8;
            cp_async16(sb + so,          Ah + goA);
            cp_async16(sb + 16384 + so,  Al + goA);
            cp_async16(sb + 32768 + so,  Bh + goB);
            cp_async16(sb + 49152 + so,  Bl + goB);
        }
        cp_commit();
    };

    // ldmatrix per-thread address components
    const int a_mtx = lane >> 3;                 // 0..3
    const int a_m_in = (a_mtx & 1) * 8 + (lane & 7);   // A: m offset within 16
    const int a_kh = (a_mtx >> 1) * 16;                // A: k-byte half offset
    const int b_n_in = (a_mtx >> 1) * 8 + (lane & 7);  // B: n offset within 16
    const int b_kh = (a_mtx & 1) * 16;                 // B: k-byte half offset

    issue(0);
    for (int c = 0; c < NC; c++) {
        if (c + 1 < NC) {
            issue(c + 1);
            asm volatile("cp.async.wait_group 1;" ::: "memory");
        } else {
            asm volatile("cp.async.wait_group 0;" ::: "memory");
        }
        __syncthreads();

        const uint32_t sb = sbase + (uint32_t)(c & 1) * 65536u;
#pragma unroll
        for (int s = 0; s < 4; s++) {
            uint32_t aH[2][4], aL[2][4], bH[4][4], bL[4][4];
#pragma unroll
            for (int mt = 0; mt < 2; mt++) {
                int m = warp_m * 32 + mt * 16 + a_m_in;
                uint32_t kb = (uint32_t)(s * 32 + a_kh);
                uint32_t off = (uint32_t)(m * 128) + (kb ^ (uint32_t)((m & 7) * 16));
                ldmatrix_x4(aH[mt], sb + off);
                ldmatrix_x4(aL[mt], sb + 16384 + off);
            }
#pragma unroll
            for (int np = 0; np < 4; np++) {
                int n = warp_n * 64 + np * 16 + b_n_in;
                uint32_t kb = (uint32_t)(s * 32 + b_kh);
                uint32_t off = (uint32_t)(n * 128) + (kb ^ (uint32_t)((n & 7) * 16));
                ldmatrix_x4(bH[np], sb + 32768 + off);
                ldmatrix_x4(bL[np], sb + 49152 + off);
            }
#pragma unroll
            for (int mt = 0; mt < 2; mt++)
#pragma unroll
                for (int np = 0; np < 4; np++)
#pragma unroll
                    for (int hf = 0; hf < 2; hf++) {
                        float* d = acc[mt][np * 2 + hf];
                        mma_bf16(d, aH[mt], &bH[np][hf * 2]);
                        mma_bf16(d, aH[mt], &bL[np][hf * 2]);
                        mma_bf16(d, aL[mt], &bH[np][hf * 2]);
                    }
        }
        __syncthreads();
    }

    // ---- epilogue: direct from registers ----
    const int er = lane >> 2;          // 0..7
    const int ec = (lane & 3) * 2;     // 0,2,4,6
#pragma unroll
    for (int mt = 0; mt < 2; mt++) {
#pragma unroll
        for (int nt = 0; nt < 8; nt++) {
            int n = colC + warp_n * 64 + nt * 8 + ec;
            float b0 = bias[n], b1 = bias[n + 1];
#pragma unroll
            for (int half = 0; half < 2; half++) {
                int m = rowC + warp_m * 32 + mt * 16 + er + half * 8;
                float v0 = acc[mt][nt][half * 2]     + b0;
                float v1 = acc[mt][nt][half * 2 + 1] + b1;
                size_t o = (size_t)m * N + n;
                if (EPI == 0) {
                    *(float2*)(Cf + o) = make_float2(v0, v1);
                } else if (EPI == 2) {
                    float2 rv = *(const float2*)(R + o);
                    *(float2*)(Cf + o) = make_float2(v0 + rv.x, v1 + rv.y);
                } else {  // gelu -> bf16 hi/lo
                    float g0 = 0.5f * v0 * (1.f + erff(v0 * 0.70710678118654752f));
                    float g1 = 0.5f * v1 * (1.f + erff(v1 * 0.70710678118654752f));
                    __nv_bfloat16 h0, l0, h1, l1;
                    split_bf16(g0, h0, l0);
                    split_bf16(g1, h1, l1);
                    __nv_bfloat162 hv; hv.x = h0; hv.y = h1;
                    __nv_bfloat162 lv; lv.x = l0; lv.y = l1;
                    *(__nv_bfloat162*)(Ch + o) = hv;
                    *(__nv_bfloat162*)(Cl + o) = lv;
                }
            }
        }
    }
}

// ---------------- weight transpose + bf16 split: W[K,N] -> WT[N,K] hi/lo -----
__global__ __launch_bounds__(256) void transpose_split(const float* __restrict__ W,
                                                       int K, int N,
                                                       __nv_bfloat16* __restrict__ Th,
                                                       __nv_bfloat16* __restrict__ Tl) {
    __shared__ float tile[32][33];
    int n0 = blockIdx.x * 32, k0 = blockIdx.y * 32;
    int tx = threadIdx.x & 31, ty = threadIdx.x >> 5;   // 32 x 8
#pragma unroll
    for (int i = 0; i < 32; i += 8)
        tile[ty + i][tx] = W[(size_t)(k0 + ty + i) * N + n0 + tx];
    __syncthreads();
#pragma unroll
    for (int i = 0; i < 32; i += 8) {
        float v = tile[tx][ty + i];
        __nv_bfloat16 hi, lo;
        split_bf16(v, hi, lo);
        size_t o = (size_t)(n0 + ty + i) * K + k0 + tx;
        Th[o] = hi;
        Tl[o] = lo;
    }
}

// ---------------- LayerNorm -> bf16 hi/lo split --------------------------------
__global__ __launch_bounds__(256) void ln_split(const float* __restrict__ in,
                                                const float* __restrict__ w,
                                                const float* __restrict__ bvec,
                                                __nv_bfloat16* __restrict__ oh,
                                                __nv_bfloat16* __restrict__ ol) {
    int row = blockIdx.x;
    const float* r = in + (size_t)row * C_;
    int tid = threadIdx.x;
    float v[4];
    float s = 0.f, ss = 0.f;
#pragma unroll
    for (int i = 0; i < 4; i++) {
        v[i] = r[tid + i * 256];
        s += v[i];
        ss += v[i] * v[i];
    }
#pragma unroll
    for (int o = 16; o; o >>= 1) {
        s  += __shfl_xor_sync(0xffffffffu, s, o);
        ss += __shfl_xor_sync(0xffffffffu, ss, o);
    }
    __shared__ float rs_[8], rss_[8];
    __shared__ float s_mean, s_rstd;
    int warp = tid >> 5, lane = tid & 31;
    if (lane == 0) { rs_[warp] = s; rss_[warp] = ss; }
    __syncthreads();
    if (tid == 0) {
        float ts = 0.f, tss = 0.f;
#pragma unroll
        for (int i = 0; i < 8; i++) { ts += rs_[i]; tss += rss_[i]; }
        float mean = ts * (1.0f / C_);
        float var = tss * (1.0f / C_) - mean * mean;
        s_mean = mean;
        s_rstd = rsqrtf(var + EPS);
    }
    __syncthreads();
    float mean = s_mean, rstd = s_rstd;
#pragma unroll
    for (int i = 0; i < 4; i++) {
        int c = tid + i * 256;
        float o = (v[i] - mean) * rstd * w[c] + bvec[c];
        __nv_bfloat16 hi, lo;
        split_bf16(o, hi, lo);
        oh[(size_t)row * C_ + c] = hi;
        ol[(size_t)row * C_ + c] = lo;
    }
}

// ---------------- Flash attention (causal, fp32) -> y hi/lo bf16 --------------
constexpr int SMEM_FLASH = 4 * 64 * 65 * 4;

__global__ __launch_bounds__(256) void flash_kernel() {
    extern __shared__ float sh[];
    float* qs = sh;
    float* ks = sh + 64 * 65;
    float* vs = sh + 2 * 64 * 65;
    float* ps = sh + 3 * 64 * 65;

    int qt = blockIdx.x;
    int bh = blockIdx.y;
    int b = bh >> 4, h = bh & 15;
    const float* base = g_qkv + (size_t)b * T_ * C3 + h * HS_;

    int tid = threadIdx.x;
    int ty = tid >> 4, tx = tid & 15;

#pragma unroll
    for (int i = 0; i < 4; i++) {
        int idx = tid + 256 * i;
        int r = idx >> 4, c4 = idx & 15;
        float4 v4 = *(const float4*)(base + (size_t)(qt * 64 + r) * C3 + c4 * 4);
        float* d = qs + r * 65 + c4 * 4;
        d[0] = v4.x; d[1] = v4.y; d[2] = v4.z; d[3] = v4.w;
    }

    float m[4], l[4], acc[4][4];
#pragma unroll
    for (int i = 0; i < 4; i++) {
        m[i] = -1e30f;
        l[i] = 0.f;
#pragma unroll
        for (int j = 0; j < 4; j++) acc[i][j] = 0.f;
    }
    __syncthreads();

    for (int kt = 0; kt <= qt; kt++) {
#pragma unroll
        for (int i = 0; i < 4; i++) {
            int idx = tid + 256 * i;
            int r = idx >> 4, c4 = idx & 15;
            const float* kp = base + C_ + (size_t)(kt * 64 + r) * C3 + c4 * 4;
            float4 k4 = *(const float4*)kp;
            float* dk = ks + r * 65 + c4 * 4;
            dk[0] = k4.x; dk[1] = k4.y; dk[2] = k4.z; dk[3] = k4.w;
            float4 v4 = *(const float4*)(kp + C_);
            float* dv = vs + r * 65 + c4 * 4;
            dv[0] = v4.x; dv[1] = v4.y; dv[2] = v4.z; dv[3] = v4.w;
        }
        __syncthreads();

        float s[4][4];
#pragma unroll
        for (int i = 0; i < 4; i++)
#pragma unroll
            for (int j = 0; j < 4; j++) s[i][j] = 0.f;
        for (int d = 0; d < 64; d++) {
            float a[4], bb[4];
#pragma unroll
            for (int i = 0; i < 4; i++) a[i] = qs[(ty * 4 + i) * 65 + d];
#pragma unroll
            for (int j = 0; j < 4; j++) bb[j] = ks[(tx * 4 + j) * 65 + d];
#pragma unroll
            for (int i = 0; i < 4; i++)
#pragma unroll
                for (int j = 0; j < 4; j++) s[i][j] += a[i] * bb[j];
        }
        bool diag = (kt == qt);
#pragma unroll
        for (int i = 0; i < 4; i++)
#pragma unroll
            for (int j = 0; j < 4; j++) {
                s[i][j] *= 0.125f;
                if (diag && (tx * 4 + j) > (ty * 4 + i)) s[i][j] = -1e30f;
            }

        float alpha[4];
#pragma unroll
        for (int i = 0; i < 4; i++) {
            float mx = s[i][0];
#pragma unroll
            for (int j = 1; j < 4; j++) mx = fmaxf(mx, s[i][j]);
#pragma unroll
            for (int o = 1; o < 16; o <<= 1)
                mx = fmaxf(mx, __shfl_xor_sync(0xffffffffu, mx, o));
            float mnew = fmaxf(m[i], mx);
            alpha[i] = __expf(m[i] - mnew);
            float sm = 0.f;
#pragma unroll
            for (int j = 0; j < 4; j++) {
                s[i][j] = __expf(s[i][j] - mnew);
                sm += s[i][j];
            }
#pragma unroll
            for (int o = 1; o < 16; o <<= 1)
                sm += __shfl_xor_sync(0xffffffffu, sm, o);
            l[i] = l[i] * alpha[i] + sm;
            m[i] = mnew;
        }

#pragma unroll
        for (int i = 0; i < 4; i++)
#pragma unroll
            for (int j = 0; j < 4; j++)
                ps[(ty * 4 + i) * 65 + tx * 4 + j] = s[i][j];
        __syncthreads();

#pragma unroll
        for (int i = 0; i < 4; i++)
#pragma unroll
            for (int j = 0; j < 4; j++) acc[i][j] *= alpha[i];
        for (int kk = 0; kk < 64; kk++) {
            float p[4], vv[4];
#pragma unroll
            for (int i = 0; i < 4; i++) p[i] = ps[(ty * 4 + i) * 65 + kk];
#pragma unroll
            for (int j = 0; j < 4; j++) vv[j] = vs[kk * 65 + tx * 4 + j];
#pragma unroll
            for (int i = 0; i < 4; i++)
#pragma unroll
                for (int j = 0; j < 4; j++) acc[i][j] += p[i] * vv[j];
        }
        __syncthreads();
    }

#pragma unroll
    for (int i = 0; i < 4; i++) {
        float inv = 1.f / l[i];
        int t = qt * 64 + ty * 4 + i;
        size_t off = (size_t)(b * T_ + t) * C_ + h * HS_ + tx * 4;
#pragma unroll
        for (int j = 0; j < 4; j++) {
            float val = acc[i][j] * inv;
            __nv_bfloat16 hi, lo;
            split_bf16(val, hi, lo);
            g_y_hi[off + j] = hi;
            g_y_lo[off + j] = lo;
        }
    }
}

// ---------------- KV quantization ---------------------------------------------
__global__ void init_absmax_kernel() {
    g_absmax[0] = 0u;
    g_absmax[1] = 0u;
}

__global__ __launch_bounds__(256) void absmax_kernel() {
    float mk = 0.f, mv = 0.f;
    int N = BT * C_;
    for (int i = blockIdx.x * blockDim.x + threadIdx.x; i < N;
         i += gridDim.x * blockDim.x) {
        int bt = i >> 10;
        int c = i & (C_ - 1);
        const float* p = g_qkv + (size_t)bt * C3;
        mk = fmaxf(mk, fabsf(p[C_ + c]));
        mv = fmaxf(mv, fabsf(p[2 * C_ + c]));
    }
#pragma unroll
    for (int o = 16; o; o >>= 1) {
        mk = fmaxf(mk, __shfl_xor_sync(0xffffffffu, mk, o));
        mv = fmaxf(mv, __shfl_xor_sync(0xffffffffu, mv, o));
    }
    __shared__ float sk_[8], sv_[8];
    int warp = threadIdx.x >> 5, lane = threadIdx.x & 31;
    if (lane == 0) { sk_[warp] = mk; sv_[warp] = mv; }
    __syncthreads();
    if (threadIdx.x == 0) {
        float tk = 0.f, tv = 0.f;
#pragma unroll
        for (int i = 0; i < 8; i++) {
            tk = fmaxf(tk, sk_[i]);
            tv = fmaxf(tv, sv_[i]);
        }
        atomicMax(&g_absmax[0], __float_as_uint(tk));
        atomicMax(&g_absmax[1], __float_as_uint(tv));
    }
}

__global__ __launch_bounds__(256) void quant_kernel(float* __restrict__ out) {
    float ak = __uint_as_float(g_absmax[0]);
    float av = __uint_as_float(g_absmax[1]);
    float sk = ak > 0.f ? ak * (1.f / 127.f) : 1.f;
    float sv = av > 0.f ? av * (1.f / 127.f) : 1.f;
    float rk = 1.f / sk, rv = 1.f / sv;
    int N = BT * C_;
    for (int idx = blockIdx.x * blockDim.x + threadIdx.x; idx < N;
         idx += gridDim.x * blockDim.x) {
        int d = idx & 63;
        int t = (idx >> 6) & 2047;
        int h = (idx >> 17) & 15;
        int b = idx >> 21;
        const float* src = g_qkv + (size_t)(b * T_ + t) * C3 + h * HS_ + d;
        float kq = fminf(fmaxf(rintf(src[C_] * rk), -127.f), 127.f);
        float vq = fminf(fmaxf(rintf(src[2 * C_] * rv), -127.f), 127.f);
        out[OFF_KQ + idx] = kq;
        out[OFF_VQ + idx] = vq;
    }
    if (blockIdx.x == 0 && threadIdx.x == 0) {
        out[OFF_KS] = sk;
        out[OFF_VS] = sv;
    }
}

// ---------------- launch --------------------------------------------------------
extern "C" void kernel_launch(void* const* d_in, const int* in_sizes, int n_in,
                              void* d_out, int out_size) {
    const float* x     = (const float*)d_in[0];
    const float* ln1_w = (const float*)d_in[1];
    const float* ln1_b = (const float*)d_in[2];
    const float* W_qkv = (const float*)d_in[3];
    const float* b_qkv = (const float*)d_in[4];
    const float* W_o   = (const float*)d_in[5];
    const float* b_o   = (const float*)d_in[6];
    const float* ln2_w = (const float*)d_in[7];
    const float* ln2_b = (const float*)d_in[8];
    const float* W_fc  = (const float*)d_in[9];
    const float* b_fc  = (const float*)d_in[10];
    const float* W_pr  = (const float*)d_in[11];
    const float* b_pr  = (const float*)d_in[12];
    float* out = (float*)d_out;

    float *qkv, *x1;
    __nv_bfloat16 *a_hi, *a_lo, *y_hi, *y_lo, *fc_hi, *fc_lo;
    __nv_bfloat16 *wqkv_hi, *wqkv_lo, *wo_hi, *wo_lo, *wfc_hi, *wfc_lo, *wpr_hi, *wpr_lo;
    cudaGetSymbolAddress((void**)&qkv, g_qkv);
    cudaGetSymbolAddress((void**)&x1, g_x1);
    cudaGetSymbolAddress((void**)&a_hi, g_a_hi);
    cudaGetSymbolAddress((void**)&a_lo, g_a_lo);
    cudaGetSymbolAddress((void**)&y_hi, g_y_hi);
    cudaGetSymbolAddress((void**)&y_lo, g_y_lo);
    cudaGetSymbolAddress((void**)&fc_hi, g_fc_hi);
    cudaGetSymbolAddress((void**)&fc_lo, g_fc_lo);
    cudaGetSymbolAddress((void**)&wqkv_hi, g_wqkv_hi);
    cudaGetSymbolAddress((void**)&wqkv_lo, g_wqkv_lo);
    cudaGetSymbolAddress((void**)&wo_hi, g_wo_hi);
    cudaGetSymbolAddress((void**)&wo_lo, g_wo_lo);
    cudaGetSymbolAddress((void**)&wfc_hi, g_wfc_hi);
    cudaGetSymbolAddress((void**)&wfc_lo, g_wfc_lo);
    cudaGetSymbolAddress((void**)&wpr_hi, g_wpr_hi);
    cudaGetSymbolAddress((void**)&wpr_lo, g_wpr_lo);

    cudaFuncSetAttribute(flash_kernel,
                         cudaFuncAttributeMaxDynamicSharedMemorySize, SMEM_FLASH);
    cudaFuncSetAttribute(mma_gemm<0>,
                         cudaFuncAttributeMaxDynamicSharedMemorySize, SMEM_GEMM);
    cudaFuncSetAttribute(mma_gemm<1>,
                         cudaFuncAttributeMaxDynamicSharedMemorySize, SMEM_GEMM);
    cudaFuncSetAttribute(mma_gemm<2>,
                         cudaFuncAttributeMaxDynamicSharedMemorySize, SMEM_GEMM);

    dim3 tb(256);
    // weight prep: W[K,N] -> W^T[N,K] bf16 hi/lo
    transpose_split<<<dim3(C3 / 32, C_ / 32), tb>>>(W_qkv, C_, C3, wqkv_hi, wqkv_lo);
    transpose_split<<<dim3(C_ / 32, C_ / 32), tb>>>(W_o, C_, C_, wo_hi, wo_lo);
    transpose_split<<<dim3(4 * C_ / 32, C_ / 32), tb>>>(W_fc, C_, 4 * C_, wfc_hi, wfc_lo);
    transpose_split<<<dim3(C_ / 32, 4 * C_ / 32), tb>>>(W_pr, 4 * C_, C_, wpr_hi, wpr_lo);

    // 1. LN1 -> bf16 split
    ln_split<<<BT, 256>>>(x, ln1_w, ln1_b, a_hi, a_lo);
    // 2. QKV GEMM (8192,1024)x(1024,3072)
    mma_gemm<0><<<dim3(C3 / 128, BT / 128), 256, SMEM_GEMM>>>(
        a_hi, a_lo, wqkv_hi, wqkv_lo, b_qkv, nullptr, qkv, nullptr, nullptr,
        BT, C3, C_);
    // 3. Causal flash attention -> y hi/lo
    flash_kernel<<<dim3(T_ / 64, B_ * H_), 256, SMEM_FLASH>>>();
    // 4. proj + residual(x) -> x1
    mma_gemm<2><<<dim3(C_ / 128, BT / 128), 256, SMEM_GEMM>>>(
        y_hi, y_lo, wo_hi, wo_lo, b_o, x, x1, nullptr, nullptr,
        BT, C_, C_);
    // 5. LN2 -> bf16 split
    ln_split<<<BT, 256>>>(x1, ln2_w, ln2_b, a_hi, a_lo);
    // 6. FC + GELU -> fc hi/lo bf16
    mma_gemm<1><<<dim3(4 * C_ / 128, BT / 128), 256, SMEM_GEMM>>>(
        a_hi, a_lo, wfc_hi, wfc_lo, b_fc, nullptr, nullptr, fc_hi, fc_lo,
        BT, 4 * C_, C_);
    // 7. proj + residual(x1) -> out
    mma_gemm<2><<<dim3(C_ / 128, BT / 128), 256, SMEM_GEMM>>>(
        fc_hi, fc_lo, wpr_hi, wpr_lo, b_pr, x1, out + OFF_X, nullptr, nullptr,
        BT, C_, 4 * C_);
    // 8-10. KV int8 quantization
    init_absmax_kernel<<<1, 1>>>();
    absmax_kernel<<<2048, 256>>>();
    quant_kernel<<<4096, 256>>>(out);
}

// round 4
// speedup vs baseline: 3.1542x; 1.4356x over previous
#include <cuda_runtime.h>
#include <cuda_bf16.h>
#include <cstdint>
#include <math.h>

// Problem constants
constexpr int B_ = 4, T_ = 2048, C_ = 1024, H_ = 16, HS_ = 64;
constexpr int BT = B_ * T_;            // 8192 rows
constexpr int C3 = 3 * C_;             // 3072
constexpr float EPS = 1e-5f;

// Output layout (concatenated float32):
constexpr int OFF_X  = 0;
constexpr int OFF_KQ = BT * C_;
constexpr int OFF_KS = OFF_KQ + BT * C_;
constexpr int OFF_VQ = OFF_KS + 1;
constexpr int OFF_VS = OFF_VQ + BT * C_;

// ---------------- scratch (device globals) -----------------------------------
__device__ float g_x1 [BT * C_];
__device__ __nv_bfloat16 g_a_hi [BT * C_],     g_a_lo [BT * C_];
__device__ __nv_bfloat16 g_y_hi [BT * C_],     g_y_lo [BT * C_];
__device__ __nv_bfloat16 g_fc_hi[BT * 4 * C_], g_fc_lo[BT * 4 * C_];
// q/k/v in [B,H,T,HS] layout, hi/lo bf16 split. q pre-scaled by 0.125.
__device__ __nv_bfloat16 g_q_hi[BT * C_], g_q_lo[BT * C_];
__device__ __nv_bfloat16 g_k_hi[BT * C_], g_k_lo[BT * C_];
__device__ __nv_bfloat16 g_v_hi[BT * C_], g_v_lo[BT * C_];
__device__ __nv_bfloat16 g_wqkv_hi[C3 * C_],    g_wqkv_lo[C3 * C_];
__device__ __nv_bfloat16 g_wo_hi  [C_ * C_],    g_wo_lo  [C_ * C_];
__device__ __nv_bfloat16 g_wfc_hi [4 * C_ * C_],g_wfc_lo [4 * C_ * C_];
__device__ __nv_bfloat16 g_wpr_hi [C_ * 4 * C_],g_wpr_lo [C_ * 4 * C_];
__device__ unsigned g_absmax[2];

// ---------------- helpers -------------------------------------------------
__device__ __forceinline__ uint32_t smem_u32(const void* p) {
    return (uint32_t)__cvta_generic_to_shared(p);
}
__device__ __forceinline__ void cp_async16(uint32_t dst, const void* src) {
    asm volatile("cp.async.cg.shared.global [%0], [%1], 16;"
                 :: "r"(dst), "l"(src) : "memory");
}
__device__ __forceinline__ void cp_commit() {
    asm volatile("cp.async.commit_group;" ::: "memory");
}
__device__ __forceinline__ void ldmatrix_x4(uint32_t* r, uint32_t addr) {
    asm volatile("ldmatrix.sync.aligned.m8n8.x4.shared.b16 {%0,%1,%2,%3}, [%4];"
                 : "=r"(r[0]), "=r"(r[1]), "=r"(r[2]), "=r"(r[3]) : "r"(addr));
}
__device__ __forceinline__ void ldmatrix_x4_trans(uint32_t* r, uint32_t addr) {
    asm volatile("ldmatrix.sync.aligned.m8n8.x4.trans.shared.b16 {%0,%1,%2,%3}, [%4];"
                 : "=r"(r[0]), "=r"(r[1]), "=r"(r[2]), "=r"(r[3]) : "r"(addr));
}
__device__ __forceinline__ void mma_bf16(float* d, const uint32_t* a, const uint32_t* b) {
    asm volatile("mma.sync.aligned.m16n8k16.row.col.f32.bf16.bf16.f32 "
                 "{%0,%1,%2,%3},{%4,%5,%6,%7},{%8,%9},{%0,%1,%2,%3};"
                 : "+f"(d[0]), "+f"(d[1]), "+f"(d[2]), "+f"(d[3])
                 : "r"(a[0]), "r"(a[1]), "r"(a[2]), "r"(a[3]),
                   "r"(b[0]), "r"(b[1]));
}
__device__ __forceinline__ void split_bf16(float v, __nv_bfloat16& hi, __nv_bfloat16& lo) {
    hi = __float2bfloat16(v);
    lo = __float2bfloat16(v - __bfloat162float(hi));
}
// pack (x,y) into hi-bf162 and lo-bf162 words
__device__ __forceinline__ void pack2_split(float x, float y, uint32_t& hi, uint32_t& lo) {
    __nv_bfloat16 hx, lx, hy, ly;
    split_bf16(x, hx, lx);
    split_bf16(y, hy, ly);
    __nv_bfloat162 h; h.x = hx; h.y = hy;
    __nv_bfloat162 l; l.x = lx; l.y = ly;
    hi = *(uint32_t*)&h;
    lo = *(uint32_t*)&l;
}
// exp(x) for x <= 0, FMA-pipe only (no MUFU). Taylor deg-4 for 2^f, f in [-.5,.5].
__device__ __forceinline__ float fast_exp(float x) {
    float t = x * 1.4426950408889634f;
    t = fmaxf(t, -126.0f);
    float z = t + 12582912.f;                    // round to nearest int
    int i = __float_as_int(z) - 0x4B400000;
    float f = t - (z - 12582912.f);
    float p = 9.6181291e-3f;
    p = fmaf(p, f, 5.5504109e-2f);
    p = fmaf(p, f, 2.4022651e-1f);
    p = fmaf(p, f, 6.9314718e-1f);
    p = fmaf(p, f, 1.0f);
    return __int_as_float(__float_as_int(p) + (i << 23));
}

// ---------------- HMMA GEMM: C[M,N] = A[M,K] @ W[K,N], B = W^T [N,K] ---------
// CTA 128x128, K-chunk 64 bf16, 8 warps (4m x 2n), warp tile 32x64.
// bf16x3 split. EPI: 1 = bias+gelu -> bf16 hi/lo; 2 = bias+residual -> f32;
//                3 = bias -> qkv scatter (q scaled 0.125, [B,H,T,HS] hi/lo)
constexpr int SMEM_GEMM = 131072;

template <int EPI>
__global__ __launch_bounds__(256, 1)
void mma_gemm(const __nv_bfloat16* __restrict__ Ah, const __nv_bfloat16* __restrict__ Al,
              const __nv_bfloat16* __restrict__ Bh, const __nv_bfloat16* __restrict__ Bl,
              const float* __restrict__ bias, const float* __restrict__ R,
              float* __restrict__ Cf,
              __nv_bfloat16* __restrict__ Ch, __nv_bfloat16* __restrict__ Cl,
              int M, int N, int K) {
    extern __shared__ __align__(1024) char smx[];
    const uint32_t sbase = smem_u32(smx);
    const int tid = threadIdx.x;
    const int wid = tid >> 5, lane = tid & 31;
    const int warp_m = wid & 3, warp_n = wid >> 2;
    const int rowC = blockIdx.y * 128, colC = blockIdx.x * 128;
    const int NC = K >> 6;

    float acc[2][8][4];
#pragma unroll
    for (int i = 0; i < 2; i++)
#pragma unroll
        for (int j = 0; j < 8; j++)
#pragma unroll
            for (int q = 0; q < 4; q++) acc[i][j][q] = 0.f;

    const int ld_r = tid >> 3;
    const int ld_seg = tid & 7;

    auto issue = [&](int c) {
        const uint32_t sb = sbase + (uint32_t)(c & 1) * 65536u;
        const int k0 = c << 6;
#pragma unroll
        for (int i = 0; i < 4; i++) {
            int r = ld_r + i * 32;
            uint32_t so = (uint32_t)(r * 128 + ((ld_seg * 16) ^ ((r & 7) * 16)));
            size_t goA = (size_t)(rowC + r) * K + k0 + ld_seg * 8;
            size_t goB = (size_t)(colC + r) * K + k0 + ld_seg * 8;
            cp_async16(sb + so,          Ah + goA);
            cp_async16(sb + 16384 + so,  Al + goA);
            cp_async16(sb + 32768 + so,  Bh + goB);
            cp_async16(sb + 49152 + so,  Bl + goB);
        }
        cp_commit();
    };

    const int a_mtx = lane >> 3;
    const int a_m_in = (a_mtx & 1) * 8 + (lane & 7);
    const int a_kh = (a_mtx >> 1) * 16;
    const int b_n_in = (a_mtx >> 1) * 8 + (lane & 7);
    const int b_kh = (a_mtx & 1) * 16;

    issue(0);
    for (int c = 0; c < NC; c++) {
        if (c + 1 < NC) {
            issue(c + 1);
            asm volatile("cp.async.wait_group 1;" ::: "memory");
        } else {
            asm volatile("cp.async.wait_group 0;" ::: "memory");
        }
        __syncthreads();

        const uint32_t sb = sbase + (uint32_t)(c & 1) * 65536u;
#pragma unroll
        for (int s = 0; s < 4; s++) {
            uint32_t aH[2][4], aL[2][4], bH[4][4], bL[4][4];
#pragma unroll
            for (int mt = 0; mt < 2; mt++) {
                int m = warp_m * 32 + mt * 16 + a_m_in;
                uint32_t kb = (uint32_t)(s * 32 + a_kh);
                uint32_t off = (uint32_t)(m * 128) + (kb ^ (uint32_t)((m & 7) * 16));
                ldmatrix_x4(aH[mt], sb + off);
                ldmatrix_x4(aL[mt], sb + 16384 + off);
            }
#pragma unroll
            for (int np = 0; np < 4; np++) {
                int n = warp_n * 64 + np * 16 + b_n_in;
                uint32_t kb = (uint32_t)(s * 32 + b_kh);
                uint32_t off = (uint32_t)(n * 128) + (kb ^ (uint32_t)((n & 7) * 16));
                ldmatrix_x4(bH[np], sb + 32768 + off);
                ldmatrix_x4(bL[np], sb + 49152 + off);
            }
#pragma unroll
            for (int mt = 0; mt < 2; mt++)
#pragma unroll
                for (int np = 0; np < 4; np++)
#pragma unroll
                    for (int hf = 0; hf < 2; hf++) {
                        float* d = acc[mt][np * 2 + hf];
                        mma_bf16(d, aH[mt], &bH[np][hf * 2]);
                        mma_bf16(d, aH[mt], &bL[np][hf * 2]);
                        mma_bf16(d, aL[mt], &bH[np][hf * 2]);
                    }
        }
        __syncthreads();
    }

    // ---- epilogue ----
    const int er = lane >> 2;
    const int ec = (lane & 3) * 2;
#pragma unroll
    for (int mt = 0; mt < 2; mt++) {
#pragma unroll
        for (int nt = 0; nt < 8; nt++) {
            int n = colC + warp_n * 64 + nt * 8 + ec;
            float b0 = bias[n], b1 = bias[n + 1];
#pragma unroll
            for (int half = 0; half < 2; half++) {
                int m = rowC + warp_m * 32 + mt * 16 + er + half * 8;
                float v0 = acc[mt][nt][half * 2]     + b0;
                float v1 = acc[mt][nt][half * 2 + 1] + b1;
                size_t o = (size_t)m * N + n;
                if (EPI == 2) {
                    float2 rv = *(const float2*)(R + o);
                    *(float2*)(Cf + o) = make_float2(v0 + rv.x, v1 + rv.y);
                } else if (EPI == 1) {  // gelu -> bf16 hi/lo
                    float g0 = 0.5f * v0 * (1.f + erff(v0 * 0.70710678118654752f));
                    float g1 = 0.5f * v1 * (1.f + erff(v1 * 0.70710678118654752f));
                    uint32_t hw, lw;
                    pack2_split(g0, g1, hw, lw);
                    *(uint32_t*)(Ch + o) = hw;
                    *(uint32_t*)(Cl + o) = lw;
                } else {  // EPI == 3: qkv scatter
                    int which = n >> 10;
                    int h = (n >> 6) & 15, d = n & 63;
                    int bb = m >> 11, t = m & 2047;
                    size_t dst = ((size_t)(bb * 16 + h) * 2048 + t) * 64 + d;
                    if (which == 0) { v0 *= 0.125f; v1 *= 0.125f; }
                    uint32_t hw, lw;
                    pack2_split(v0, v1, hw, lw);
                    __nv_bfloat16* ph = (which == 0) ? g_q_hi : (which == 1) ? g_k_hi : g_v_hi;
                    __nv_bfloat16* pl = (which == 0) ? g_q_lo : (which == 1) ? g_k_lo : g_v_lo;
                    *(uint32_t*)(ph + dst) = hw;
                    *(uint32_t*)(pl + dst) = lw;
                }
            }
        }
    }
}

// ---------------- weight transpose + bf16 split ------------------------------
__global__ __launch_bounds__(256) void transpose_split(const float* __restrict__ W,
                                                       int K, int N,
                                                       __nv_bfloat16* __restrict__ Th,
                                                       __nv_bfloat16* __restrict__ Tl) {
    __shared__ float tile[32][33];
    int n0 = blockIdx.x * 32, k0 = blockIdx.y * 32;
    int tx = threadIdx.x & 31, ty = threadIdx.x >> 5;
#pragma unroll
    for (int i = 0; i < 32; i += 8)
        tile[ty + i][tx] = W[(size_t)(k0 + ty + i) * N + n0 + tx];
    __syncthreads();
#pragma unroll
    for (int i = 0; i < 32; i += 8) {
        float v = tile[tx][ty + i];
        __nv_bfloat16 hi, lo;
        split_bf16(v, hi, lo);
        size_t o = (size_t)(n0 + ty + i) * K + k0 + tx;
        Th[o] = hi;
        Tl[o] = lo;
    }
}

// ---------------- LayerNorm -> bf16 hi/lo split --------------------------------
__global__ __launch_bounds__(256) void ln_split(const float* __restrict__ in,
                                                const float* __restrict__ w,
                                                const float* __restrict__ bvec,
                                                __nv_bfloat16* __restrict__ oh,
                                                __nv_bfloat16* __restrict__ ol) {
    int row = blockIdx.x;
    const float* r = in + (size_t)row * C_;
    int tid = threadIdx.x;
    float v[4];
    float s = 0.f, ss = 0.f;
#pragma unroll
    for (int i = 0; i < 4; i++) {
        v[i] = r[tid + i * 256];
        s += v[i];
        ss += v[i] * v[i];
    }
#pragma unroll
    for (int o = 16; o; o >>= 1) {
        s  += __shfl_xor_sync(0xffffffffu, s, o);
        ss += __shfl_xor_sync(0xffffffffu, ss, o);
    }
    __shared__ float rs_[8], rss_[8];
    __shared__ float s_mean, s_rstd;
    int warp = tid >> 5, lane = tid & 31;
    if (lane == 0) { rs_[warp] = s; rss_[warp] = ss; }
    __syncthreads();
    if (tid == 0) {
        float ts = 0.f, tss = 0.f;
#pragma unroll
        for (int i = 0; i < 8; i++) { ts += rs_[i]; tss += rss_[i]; }
        float mean = ts * (1.0f / C_);
        float var = tss * (1.0f / C_) - mean * mean;
        s_mean = mean;
        s_rstd = rsqrtf(var + EPS);
    }
    __syncthreads();
    float mean = s_mean, rstd = s_rstd;
#pragma unroll
    for (int i = 0; i < 4; i++) {
        int c = tid + i * 256;
        float o = (v[i] - mean) * rstd * w[c] + bvec[c];
        __nv_bfloat16 hi, lo;
        split_bf16(o, hi, lo);
        oh[(size_t)row * C_ + c] = hi;
        ol[(size_t)row * C_ + c] = lo;
    }
}

// ---------------- HMMA flash attention (causal) --------------------------------
// CTA: 128 q-rows x 64-key tiles, 8 warps (16 q-rows each), grid (T/128, B*H).
// smem: Qhi 16K | Qlo 16K | 2 x (Khi 8K | Klo 8K | Vhi 8K | Vlo 8K) = 96KB
constexpr int SMEM_FLASH = 98304;

__global__ __launch_bounds__(256, 1) void flash2() {
    extern __shared__ __align__(1024) char smx[];
    const uint32_t sbase = smem_u32(smx);
    const int tid = threadIdx.x, wid = tid >> 5, lane = tid & 31;
    const int qt = blockIdx.x, bh = blockIdx.y;
    const int q0 = qt * 128;
    const size_t hbase = (size_t)bh * (T_ * HS_);

    // Q tiles -> smem (group 0)
    {
        const __nv_bfloat16* qh = g_q_hi + hbase + (size_t)q0 * 64;
        const __nv_bfloat16* ql = g_q_lo + hbase + (size_t)q0 * 64;
#pragma unroll
        for (int i = 0; i < 4; i++) {
            int u = tid + 256 * i;
            int r = u >> 3, seg = u & 7;
            uint32_t so = (uint32_t)(r * 128 + ((seg * 16) ^ ((r & 7) * 16)));
            cp_async16(sbase + so,         qh + r * 64 + seg * 8);
            cp_async16(sbase + 16384 + so, ql + r * 64 + seg * 8);
        }
        cp_commit();
    }

    auto load_kv = [&](int kt) {
        uint32_t sb = sbase + 32768u + (uint32_t)(kt & 1) * 32768u;
        const size_t kb = hbase + (size_t)kt * 64 * 64;
#pragma unroll
        for (int i = 0; i < 2; i++) {
            int u = tid + 256 * i;
            int r = u >> 3, seg = u & 7;
            uint32_t so = (uint32_t)(r * 128 + ((seg * 16) ^ ((r & 7) * 16)));
            size_t go = kb + r * 64 + seg * 8;
            cp_async16(sb + so,         g_k_hi + go);
            cp_async16(sb + 8192 + so,  g_k_lo + go);
            cp_async16(sb + 16384 + so, g_v_hi + go);
            cp_async16(sb + 24576 + so, g_v_lo + go);
        }
        cp_commit();
    };

    load_kv(0);
    asm volatile("cp.async.wait_group 1;" ::: "memory");  // Q done
    __syncthreads();

    // Q fragments (held in regs for all kt)
    uint32_t qh[4][4], ql[4][4];
    {
        const int a_mtx = lane >> 3;
        const int a_m = wid * 16 + (a_mtx & 1) * 8 + (lane & 7);
        const int a_kh = (a_mtx >> 1) * 16;
#pragma unroll
        for (int s = 0; s < 4; s++) {
            uint32_t kb = (uint32_t)(s * 32 + a_kh);
            uint32_t off = (uint32_t)(a_m * 128) + (kb ^ (uint32_t)((a_m & 7) * 16));
            ldmatrix_x4(qh[s], sbase + off);
            ldmatrix_x4(ql[s], sbase + 16384 + off);
        }
    }

    const int ktmax = qt * 2 + 1;
    float m0 = -1e30f, m1 = -1e30f, l0 = 0.f, l1 = 0.f;
    float acc[8][4];
#pragma unroll
    for (int i = 0; i < 8; i++)
#pragma unroll
        for (int j = 0; j < 4; j++) acc[i][j] = 0.f;

    const int b_mtx = lane >> 3;
    const int kn_in = (b_mtx >> 1) * 8 + (lane & 7);   // K frag n-within-16
    const int kk_h = (b_mtx & 1) * 16;                  // K frag k-byte half
    const int v_row_in = (b_mtx & 1) * 8 + (lane & 7);  // V frag key-within-16
    const int v_col = (b_mtx >> 1) * 16;                // V frag d-bytes within 32
    const int row0 = q0 + wid * 16 + (lane >> 2);

    for (int kt = 0; kt <= ktmax; kt++) {
        if (kt < ktmax) {
            load_kv(kt + 1);
            asm volatile("cp.async.wait_group 1;" ::: "memory");
        } else {
            asm volatile("cp.async.wait_group 0;" ::: "memory");
        }
        __syncthreads();
        const uint32_t sb = sbase + 32768u + (uint32_t)(kt & 1) * 32768u;

        // ---- S = Qhi(Khi+Klo) + Qlo*Khi ----
        float S[8][4];
#pragma unroll
        for (int i = 0; i < 8; i++)
#pragma unroll
            for (int j = 0; j < 4; j++) S[i][j] = 0.f;
#pragma unroll
        for (int s = 0; s < 4; s++) {
            uint32_t kf[4][4];
#pragma unroll
            for (int g = 0; g < 4; g++) {
                int n = g * 16 + kn_in;
                uint32_t kb = (uint32_t)(s * 32 + kk_h);
                uint32_t off = (uint32_t)(n * 128) + (kb ^ (uint32_t)((n & 7) * 16));
                ldmatrix_x4(kf[g], sb + off);
            }
#pragma unroll
            for (int nt = 0; nt < 8; nt++) {
                mma_bf16(S[nt], qh[s], &kf[nt >> 1][(nt & 1) * 2]);
                mma_bf16(S[nt], ql[s], &kf[nt >> 1][(nt & 1) * 2]);
            }
#pragma unroll
            for (int g = 0; g < 4; g++) {
                int n = g * 16 + kn_in;
                uint32_t kb = (uint32_t)(s * 32 + kk_h);
                uint32_t off = (uint32_t)(n * 128) + (kb ^ (uint32_t)((n & 7) * 16));
                ldmatrix_x4(kf[g], sb + 8192 + off);
            }
#pragma unroll
            for (int nt = 0; nt < 8; nt++)
                mma_bf16(S[nt], qh[s], &kf[nt >> 1][(nt & 1) * 2]);
        }

        // ---- causal mask (only in diagonal tiles) ----
        if (kt >= 2 * qt) {
#pragma unroll
            for (int nt = 0; nt < 8; nt++) {
                int col = kt * 64 + nt * 8 + (lane & 3) * 2;
                if (col > row0)          S[nt][0] = -1e30f;
                if (col + 1 > row0)      S[nt][1] = -1e30f;
                if (col > row0 + 8)      S[nt][2] = -1e30f;
                if (col + 1 > row0 + 8)  S[nt][3] = -1e30f;
            }
        }

        // ---- online softmax (FMA-pipe exp) ----
        float mx0 = -1e30f, mx1 = -1e30f;
#pragma unroll
        for (int nt = 0; nt < 8; nt++) {
            mx0 = fmaxf(mx0, fmaxf(S[nt][0], S[nt][1]));
            mx1 = fmaxf(mx1, fmaxf(S[nt][2], S[nt][3]));
        }
        mx0 = fmaxf(mx0, __shfl_xor_sync(0xffffffffu, mx0, 1));
        mx0 = fmaxf(mx0, __shfl_xor_sync(0xffffffffu, mx0, 2));
        mx1 = fmaxf(mx1, __shfl_xor_sync(0xffffffffu, mx1, 1));
        mx1 = fmaxf(mx1, __shfl_xor_sync(0xffffffffu, mx1, 2));
        float mn0 = fmaxf(m0, mx0), mn1 = fmaxf(m1, mx1);
        float al0 = fast_exp(m0 - mn0), al1 = fast_exp(m1 - mn1);
        m0 = mn0; m1 = mn1;
        float sm0 = 0.f, sm1 = 0.f;
#pragma unroll
        for (int nt = 0; nt < 8; nt++) {
            S[nt][0] = fast_exp(S[nt][0] - mn0);
            S[nt][1] = fast_exp(S[nt][1] - mn0);
            S[nt][2] = fast_exp(S[nt][2] - mn1);
            S[nt][3] = fast_exp(S[nt][3] - mn1);
            sm0 += S[nt][0] + S[nt][1];
            sm1 += S[nt][2] + S[nt][3];
        }
        sm0 += __shfl_xor_sync(0xffffffffu, sm0, 1);
        sm0 += __shfl_xor_sync(0xffffffffu, sm0, 2);
        sm1 += __shfl_xor_sync(0xffffffffu, sm1, 1);
        sm1 += __shfl_xor_sync(0xffffffffu, sm1, 2);
        l0 = l0 * al0 + sm0;
        l1 = l1 * al1 + sm1;
#pragma unroll
        for (int nt = 0; nt < 8; nt++) {
            acc[nt][0] *= al0; acc[nt][1] *= al0;
            acc[nt][2] *= al1; acc[nt][3] *= al1;
        }

        // ---- pack P into A-fragments (hi/lo) ----
        uint32_t ph[4][4], pl[4][4];
#pragma unroll
        for (int s = 0; s < 4; s++) {
            pack2_split(S[2 * s][0],     S[2 * s][1],     ph[s][0], pl[s][0]);
            pack2_split(S[2 * s][2],     S[2 * s][3],     ph[s][1], pl[s][1]);
            pack2_split(S[2 * s + 1][0], S[2 * s + 1][1], ph[s][2], pl[s][2]);
            pack2_split(S[2 * s + 1][2], S[2 * s + 1][3], ph[s][3], pl[s][3]);
        }

        // ---- acc += Phi(Vhi+Vlo) + Plo*Vhi ----
#pragma unroll
        for (int s = 0; s < 4; s++) {
            uint32_t vf[4][4];
#pragma unroll
            for (int g = 0; g < 4; g++) {
                int row = s * 16 + v_row_in;
                uint32_t cb = (uint32_t)(g * 32 + v_col);
                uint32_t off = (uint32_t)(row * 128) + (cb ^ (uint32_t)((row & 7) * 16));
                ldmatrix_x4_trans(vf[g], sb + 16384 + off);
            }
#pragma unroll
            for (int nt = 0; nt < 8; nt++) {
                mma_bf16(acc[nt], ph[s], &vf[nt >> 1][(nt & 1) * 2]);
                mma_bf16(acc[nt], pl[s], &vf[nt >> 1][(nt & 1) * 2]);
            }
#pragma unroll
            for (int g = 0; g < 4; g++) {
                int row = s * 16 + v_row_in;
                uint32_t cb = (uint32_t)(g * 32 + v_col);
                uint32_t off = (uint32_t)(row * 128) + (cb ^ (uint32_t)((row & 7) * 16));
                ldmatrix_x4_trans(vf[g], sb + 24576 + off);
            }
#pragma unroll
            for (int nt = 0; nt < 8; nt++)
                mma_bf16(acc[nt], ph[s], &vf[nt >> 1][(nt & 1) * 2]);
        }
        __syncthreads();
    }

    // ---- epilogue: y = acc / l -> g_y hi/lo [B,T,C] ----
    float inv0 = 1.f / l0, inv1 = 1.f / l1;
    int b = bh >> 4, h = bh & 15;
#pragma unroll
    for (int nt = 0; nt < 8; nt++) {
        int d = nt * 8 + (lane & 3) * 2;
        size_t o0 = (size_t)(b * 2048 + row0) * 1024 + h * 64 + d;
        uint32_t hw, lw;
        pack2_split(acc[nt][0] * inv0, acc[nt][1] * inv0, hw, lw);
        *(uint32_t*)(g_y_hi + o0) = hw;
        *(uint32_t*)(g_y_lo + o0) = lw;
        size_t o1 = o0 + 8 * 1024;
        pack2_split(acc[nt][2] * inv1, acc[nt][3] * inv1, hw, lw);
        *(uint32_t*)(g_y_hi + o1) = hw;
        *(uint32_t*)(g_y_lo + o1) = lw;
    }
}

// ---------------- KV quantization ---------------------------------------------
__global__ void init_absmax_kernel() {
    g_absmax[0] = 0u;
    g_absmax[1] = 0u;
}

__global__ __launch_bounds__(256) void absmax_kernel() {
    float mk = 0.f, mv = 0.f;
    int N = BT * C_;
    for (int i = blockIdx.x * blockDim.x + threadIdx.x; i < N;
         i += gridDim.x * blockDim.x) {
        float kk = __bfloat162float(g_k_hi[i]) + __bfloat162float(g_k_lo[i]);
        float vv = __bfloat162float(g_v_hi[i]) + __bfloat162float(g_v_lo[i]);
        mk = fmaxf(mk, fabsf(kk));
        mv = fmaxf(mv, fabsf(vv));
    }
#pragma unroll
    for (int o = 16; o; o >>= 1) {
        mk = fmaxf(mk, __shfl_xor_sync(0xffffffffu, mk, o));
        mv = fmaxf(mv, __shfl_xor_sync(0xffffffffu, mv, o));
    }
    __shared__ float sk_[8], sv_[8];
    int warp = threadIdx.x >> 5, lane = threadIdx.x & 31;
    if (lane == 0) { sk_[warp] = mk; sv_[warp] = mv; }
    __syncthreads();
    if (threadIdx.x == 0) {
        float tk = 0.f, tv = 0.f;
#pragma unroll
        for (int i = 0; i < 8; i++) {
            tk = fmaxf(tk, sk_[i]);
            tv = fmaxf(tv, sv_[i]);
        }
        atomicMax(&g_absmax[0], __float_as_uint(tk));
        atomicMax(&g_absmax[1], __float_as_uint(tv));
    }
}

__global__ __launch_bounds__(256) void quant_kernel(float* __restrict__ out) {
    float ak = __uint_as_float(g_absmax[0]);
    float av = __uint_as_float(g_absmax[1]);
    float sk = ak > 0.f ? ak * (1.f / 127.f) : 1.f;
    float sv = av > 0.f ? av * (1.f / 127.f) : 1.f;
    float rk = 1.f / sk, rv = 1.f / sv;
    int N = BT * C_;
    for (int idx = blockIdx.x * blockDim.x + threadIdx.x; idx < N;
         idx += gridDim.x * blockDim.x) {
        float kk = __bfloat162float(g_k_hi[idx]) + __bfloat162float(g_k_lo[idx]);
        float vv = __bfloat162float(g_v_hi[idx]) + __bfloat162float(g_v_lo[idx]);
        out[OFF_KQ + idx] = fminf(fmaxf(rintf(kk * rk), -127.f), 127.f);
        out[OFF_VQ + idx] = fminf(fmaxf(rintf(vv * rv), -127.f), 127.f);
    }
    if (blockIdx.x == 0 && threadIdx.x == 0) {
        out[OFF_KS] = sk;
        out[OFF_VS] = sv;
    }
}

// ---------------- launch --------------------------------------------------------
extern "C" void kernel_launch(void* const* d_in, const int* in_sizes, int n_in,
                              void* d_out, int out_size) {
    const float* x     = (const float*)d_in[0];
    const float* ln1_w = (const float*)d_in[1];
    const float* ln1_b = (const float*)d_in[2];
    const float* W_qkv = (const float*)d_in[3];
    const float* b_qkv = (const float*)d_in[4];
    const float* W_o   = (const float*)d_in[5];
    const float* b_o   = (const float*)d_in[6];
    const float* ln2_w = (const float*)d_in[7];
    const float* ln2_b = (const float*)d_in[8];
    const float* W_fc  = (const float*)d_in[9];
    const float* b_fc  = (const float*)d_in[10];
    const float* W_pr  = (const float*)d_in[11];
    const float* b_pr  = (const float*)d_in[12];
    float* out = (float*)d_out;

    float *x1;
    __nv_bfloat16 *a_hi, *a_lo, *y_hi, *y_lo, *fc_hi, *fc_lo;
    __nv_bfloat16 *wqkv_hi, *wqkv_lo, *wo_hi, *wo_lo, *wfc_hi, *wfc_lo, *wpr_hi, *wpr_lo;
    cudaGetSymbolAddress((void**)&x1, g_x1);
    cudaGetSymbolAddress((void**)&a_hi, g_a_hi);
    cudaGetSymbolAddress((void**)&a_lo, g_a_lo);
    cudaGetSymbolAddress((void**)&y_hi, g_y_hi);
    cudaGetSymbolAddress((void**)&y_lo, g_y_lo);
    cudaGetSymbolAddress((void**)&fc_hi, g_fc_hi);
    cudaGetSymbolAddress((void**)&fc_lo, g_fc_lo);
    cudaGetSymbolAddress((void**)&wqkv_hi, g_wqkv_hi);
    cudaGetSymbolAddress((void**)&wqkv_lo, g_wqkv_lo);
    cudaGetSymbolAddress((void**)&wo_hi, g_wo_hi);
    cudaGetSymbolAddress((void**)&wo_lo, g_wo_lo);
    cudaGetSymbolAddress((void**)&wfc_hi, g_wfc_hi);
    cudaGetSymbolAddress((void**)&wfc_lo, g_wfc_lo);
    cudaGetSymbolAddress((void**)&wpr_hi, g_wpr_hi);
    cudaGetSymbolAddress((void**)&wpr_lo, g_wpr_lo);

    cudaFuncSetAttribute(flash2,
                         cudaFuncAttributeMaxDynamicSharedMemorySize, SMEM_FLASH);
    cudaFuncSetAttribute(mma_gemm<1>,
                         cudaFuncAttributeMaxDynamicSharedMemorySize, SMEM_GEMM);
    cudaFuncSetAttribute(mma_gemm<2>,
                         cudaFuncAttributeMaxDynamicSharedMemorySize, SMEM_GEMM);
    cudaFuncSetAttribute(mma_gemm<3>,
                         cudaFuncAttributeMaxDynamicSharedMemorySize, SMEM_GEMM);

    dim3 tb(256);
    // weight prep: W[K,N] -> W^T[N,K] bf16 hi/lo
    transpose_split<<<dim3(C3 / 32, C_ / 32), tb>>>(W_qkv, C_, C3, wqkv_hi, wqkv_lo);
    transpose_split<<<dim3(C_ / 32, C_ / 32), tb>>>(W_o, C_, C_, wo_hi, wo_lo);
    transpose_split<<<dim3(4 * C_ / 32, C_ / 32), tb>>>(W_fc, C_, 4 * C_, wfc_hi, wfc_lo);
    transpose_split<<<dim3(C_ / 32, 4 * C_ / 32), tb>>>(W_pr, 4 * C_, C_, wpr_hi, wpr_lo);

    // 1. LN1 -> bf16 split
    ln_split<<<BT, 256>>>(x, ln1_w, ln1_b, a_hi, a_lo);
    // 2. QKV GEMM -> scatter q/k/v hi/lo [B,H,T,HS] (q scaled 0.125)
    mma_gemm<3><<<dim3(C3 / 128, BT / 128), 256, SMEM_GEMM>>>(
        a_hi, a_lo, wqkv_hi, wqkv_lo, b_qkv, nullptr, nullptr, nullptr, nullptr,
        BT, C3, C_);
    // 3. HMMA causal flash attention -> y hi/lo
    flash2<<<dim3(T_ / 128, B_ * H_), 256, SMEM_FLASH>>>();
    // 4. proj + residual(x) -> x1
    mma_gemm<2><<<dim3(C_ / 128, BT / 128), 256, SMEM_GEMM>>>(
        y_hi, y_lo, wo_hi, wo_lo, b_o, x, x1, nullptr, nullptr,
        BT, C_, C_);
    // 5. LN2 -> bf16 split
    ln_split<<<BT, 256>>>(x1, ln2_w, ln2_b, a_hi, a_lo);
    // 6. FC + GELU -> fc hi/lo bf16
    mma_gemm<1><<<dim3(4 * C_ / 128, BT / 128), 256, SMEM_GEMM>>>(
        a_hi, a_lo, wfc_hi, wfc_lo, b_fc, nullptr, nullptr, fc_hi, fc_lo,
        BT, 4 * C_, C_);
    // 7. proj + residual(x1) -> out
    mma_gemm<2><<<dim3(C_ / 128, BT / 128), 256, SMEM_GEMM>>>(
        fc_hi, fc_lo, wpr_hi, wpr_lo, b_pr, x1, out + OFF_X, nullptr, nullptr,
        BT, C_, 4 * C_);
    // 8-10. KV int8 quantization
    init_absmax_kernel<<<1, 1>>>();
    absmax_kernel<<<2048, 256>>>();
    quant_kernel<<<4096, 256>>>(out);
}

// round 5
// speedup vs baseline: 3.4246x; 1.0857x over previous
#include <cuda_runtime.h>
#include <cuda_bf16.h>
#include <cstdint>
#include <math.h>

// Problem constants
constexpr int B_ = 4, T_ = 2048, C_ = 1024, H_ = 16, HS_ = 64;
constexpr int BT = B_ * T_;            // 8192 rows
constexpr int C3 = 3 * C_;             // 3072
constexpr float EPS = 1e-5f;

// Output layout (concatenated float32):
constexpr int OFF_X  = 0;
constexpr int OFF_KQ = BT * C_;
constexpr int OFF_KS = OFF_KQ + BT * C_;
constexpr int OFF_VQ = OFF_KS + 1;
constexpr int OFF_VS = OFF_VQ + BT * C_;

// ---------------- scratch (device globals) -----------------------------------
__device__ float g_x1 [BT * C_];
__device__ __nv_bfloat16 g_a_hi [BT * C_],     g_a_lo [BT * C_];
__device__ __nv_bfloat16 g_y_hi [BT * C_],     g_y_lo [BT * C_];
__device__ __nv_bfloat16 g_fc_hi[BT * 4 * C_], g_fc_lo[BT * 4 * C_];
// q/k/v in [B,H,T,HS] layout, hi/lo bf16 split. q pre-scaled by 0.125.
__device__ __nv_bfloat16 g_q_hi[BT * C_], g_q_lo[BT * C_];
__device__ __nv_bfloat16 g_k_hi[BT * C_], g_k_lo[BT * C_];
__device__ __nv_bfloat16 g_v_hi[BT * C_], g_v_lo[BT * C_];
__device__ __nv_bfloat16 g_wqkv_hi[C3 * C_],    g_wqkv_lo[C3 * C_];
__device__ __nv_bfloat16 g_wo_hi  [C_ * C_],    g_wo_lo  [C_ * C_];
__device__ __nv_bfloat16 g_wfc_hi [4 * C_ * C_],g_wfc_lo [4 * C_ * C_];
__device__ __nv_bfloat16 g_wpr_hi [C_ * 4 * C_],g_wpr_lo [C_ * 4 * C_];
__device__ unsigned g_absmax[2];

// ---------------- helpers -------------------------------------------------
__device__ __forceinline__ uint32_t smem_u32(const void* p) {
    return (uint32_t)__cvta_generic_to_shared(p);
}
__device__ __forceinline__ void cp_async16(uint32_t dst, const void* src) {
    asm volatile("cp.async.cg.shared.global [%0], [%1], 16;"
                 :: "r"(dst), "l"(src) : "memory");
}
__device__ __forceinline__ void cp_commit() {
    asm volatile("cp.async.commit_group;" ::: "memory");
}
__device__ __forceinline__ void ldmatrix_x4(uint32_t* r, uint32_t addr) {
    asm volatile("ldmatrix.sync.aligned.m8n8.x4.shared.b16 {%0,%1,%2,%3}, [%4];"
                 : "=r"(r[0]), "=r"(r[1]), "=r"(r[2]), "=r"(r[3]) : "r"(addr));
}
__device__ __forceinline__ void ldmatrix_x4_trans(uint32_t* r, uint32_t addr) {
    asm volatile("ldmatrix.sync.aligned.m8n8.x4.trans.shared.b16 {%0,%1,%2,%3}, [%4];"
                 : "=r"(r[0]), "=r"(r[1]), "=r"(r[2]), "=r"(r[3]) : "r"(addr));
}
__device__ __forceinline__ void mma_bf16(float* d, const uint32_t* a, const uint32_t* b) {
    asm volatile("mma.sync.aligned.m16n8k16.row.col.f32.bf16.bf16.f32 "
                 "{%0,%1,%2,%3},{%4,%5,%6,%7},{%8,%9},{%0,%1,%2,%3};"
                 : "+f"(d[0]), "+f"(d[1]), "+f"(d[2]), "+f"(d[3])
                 : "r"(a[0]), "r"(a[1]), "r"(a[2]), "r"(a[3]),
                   "r"(b[0]), "r"(b[1]));
}
__device__ __forceinline__ void split_bf16(float v, __nv_bfloat16& hi, __nv_bfloat16& lo) {
    hi = __float2bfloat16(v);
    lo = __float2bfloat16(v - __bfloat162float(hi));
}
__device__ __forceinline__ void pack2_split(float x, float y, uint32_t& hi, uint32_t& lo) {
    __nv_bfloat16 hx, lx, hy, ly;
    split_bf16(x, hx, lx);
    split_bf16(y, hy, ly);
    __nv_bfloat162 h; h.x = hx; h.y = hy;
    __nv_bfloat162 l; l.x = lx; l.y = ly;
    hi = *(uint32_t*)&h;
    lo = *(uint32_t*)&l;
}
// exp(x), FMA-pipe only (no MUFU).
__device__ __forceinline__ float fast_exp(float x) {
    float t = x * 1.4426950408889634f;
    t = fmaxf(t, -126.0f);
    float z = t + 12582912.f;
    int i = __float_as_int(z) - 0x4B400000;
    float f = t - (z - 12582912.f);
    float p = 9.6181291e-3f;
    p = fmaf(p, f, 5.5504109e-2f);
    p = fmaf(p, f, 2.4022651e-1f);
    p = fmaf(p, f, 6.9314718e-1f);
    p = fmaf(p, f, 1.0f);
    return __int_as_float(__float_as_int(p) + (i << 23));
}

// ---------------- HMMA GEMM: C[M,N] = A[M,K] @ W[K,N], B = W^T [N,K] ---------
// CTA 128x128, K-chunk 32 bf16 (64B rows), 3-stage cp.async pipeline,
// 2 CTAs/SM. 8 warps (4m x 2n), warp tile 32x64. bf16x3 split.
// Stage: Ah 8K | Al 8K | Bh 8K | Bl 8K = 32KB. 3 stages = 96KB.
constexpr int GSTAGE = 32768;
constexpr int SMEM_GEMM = 3 * GSTAGE;   // 98304

template <int EPI>
__global__ __launch_bounds__(256, 2)
void mma_gemm(const __nv_bfloat16* __restrict__ Ah, const __nv_bfloat16* __restrict__ Al,
              const __nv_bfloat16* __restrict__ Bh, const __nv_bfloat16* __restrict__ Bl,
              const float* __restrict__ bias, const float* __restrict__ R,
              float* __restrict__ Cf,
              __nv_bfloat16* __restrict__ Ch, __nv_bfloat16* __restrict__ Cl,
              int M, int N, int K) {
    extern __shared__ __align__(1024) char smx[];
    const uint32_t sbase = smem_u32(smx);
    const int tid = threadIdx.x;
    const int wid = tid >> 5, lane = tid & 31;
    const int warp_m = wid & 3, warp_n = wid >> 2;
    const int rowC = blockIdx.y * 128, colC = blockIdx.x * 128;
    const int NC = K >> 5;   // K / 32

    float acc[2][8][4];
#pragma unroll
    for (int i = 0; i < 2; i++)
#pragma unroll
        for (int j = 0; j < 8; j++)
#pragma unroll
            for (int q = 0; q < 4; q++) acc[i][j][q] = 0.f;

    // cp.async mapping: u = tid + 256*i -> r = u>>2 (0..127), seg = u&3 (16B)
    const int ld_r = tid >> 2;
    const int ld_seg = tid & 3;

    auto issue = [&](int c) {
        const uint32_t sb = sbase + (uint32_t)(c % 3) * (uint32_t)GSTAGE;
        const int k0 = c << 5;
#pragma unroll
        for (int i = 0; i < 2; i++) {
            int r = ld_r + i * 64;
            uint32_t so = (uint32_t)(r * 64 + ((ld_seg ^ ((r >> 1) & 3)) * 16));
            size_t goA = (size_t)(rowC + r) * K + k0 + ld_seg * 8;
            size_t goB = (size_t)(colC + r) * K + k0 + ld_seg * 8;
            cp_async16(sb + so,          Ah + goA);
            cp_async16(sb + 8192 + so,   Al + goA);
            cp_async16(sb + 16384 + so,  Bh + goB);
            cp_async16(sb + 24576 + so,  Bl + goB);
        }
        cp_commit();
    };

    const int a_mtx = lane >> 3;
    const int a_m_in = (a_mtx & 1) * 8 + (lane & 7);
    const int a_sh = (a_mtx >> 1);                 // k 16B-half
    const int b_n_in = (a_mtx >> 1) * 8 + (lane & 7);
    const int b_sh = (a_mtx & 1);

    issue(0);
    issue(1);
    for (int c = 0; c < NC; c++) {
        if (c + 1 < NC) {
            asm volatile("cp.async.wait_group 1;" ::: "memory");
        } else {
            asm volatile("cp.async.wait_group 0;" ::: "memory");
        }
        __syncthreads();

        const uint32_t sb = sbase + (uint32_t)(c % 3) * (uint32_t)GSTAGE;
#pragma unroll
        for (int s = 0; s < 2; s++) {
            uint32_t aH[2][4], aL[2][4];
#pragma unroll
            for (int mt = 0; mt < 2; mt++) {
                int m = warp_m * 32 + mt * 16 + a_m_in;
                int seg = s * 2 + a_sh;
                uint32_t off = (uint32_t)(m * 64 + ((seg ^ ((m >> 1) & 3)) * 16));
                ldmatrix_x4(aH[mt], sb + off);
                ldmatrix_x4(aL[mt], sb + 8192 + off);
            }
#pragma unroll
            for (int np = 0; np < 4; np++) {
                uint32_t bH[4], bL[4];
                int n = warp_n * 64 + np * 16 + b_n_in;
                int seg = s * 2 + b_sh;
                uint32_t off = (uint32_t)(n * 64 + ((seg ^ ((n >> 1) & 3)) * 16));
                ldmatrix_x4(bH, sb + 16384 + off);
                ldmatrix_x4(bL, sb + 24576 + off);
#pragma unroll
                for (int mt = 0; mt < 2; mt++)
#pragma unroll
                    for (int hf = 0; hf < 2; hf++) {
                        float* d = acc[mt][np * 2 + hf];
                        mma_bf16(d, aH[mt], &bH[hf * 2]);
                        mma_bf16(d, aH[mt], &bL[hf * 2]);
                        mma_bf16(d, aL[mt], &bH[hf * 2]);
                    }
            }
        }
        if (c + 2 < NC) issue(c + 2);
        __syncthreads();
    }

    // ---- epilogue ----
    const int er = lane >> 2;
    const int ec = (lane & 3) * 2;
#pragma unroll
    for (int mt = 0; mt < 2; mt++) {
#pragma unroll
        for (int nt = 0; nt < 8; nt++) {
            int n = colC + warp_n * 64 + nt * 8 + ec;
            float b0 = bias[n], b1 = bias[n + 1];
#pragma unroll
            for (int half = 0; half < 2; half++) {
                int m = rowC + warp_m * 32 + mt * 16 + er + half * 8;
                float v0 = acc[mt][nt][half * 2]     + b0;
                float v1 = acc[mt][nt][half * 2 + 1] + b1;
                size_t o = (size_t)m * N + n;
                if (EPI == 2) {
                    float2 rv = *(const float2*)(R + o);
                    *(float2*)(Cf + o) = make_float2(v0 + rv.x, v1 + rv.y);
                } else if (EPI == 1) {  // gelu -> bf16 hi/lo
                    float g0 = 0.5f * v0 * (1.f + erff(v0 * 0.70710678118654752f));
                    float g1 = 0.5f * v1 * (1.f + erff(v1 * 0.70710678118654752f));
                    uint32_t hw, lw;
                    pack2_split(g0, g1, hw, lw);
                    *(uint32_t*)(Ch + o) = hw;
                    *(uint32_t*)(Cl + o) = lw;
                } else {  // EPI == 3: qkv scatter
                    int which = n >> 10;
                    int h = (n >> 6) & 15, d = n & 63;
                    int bb = m >> 11, t = m & 2047;
                    size_t dst = ((size_t)(bb * 16 + h) * 2048 + t) * 64 + d;
                    if (which == 0) { v0 *= 0.125f; v1 *= 0.125f; }
                    uint32_t hw, lw;
                    pack2_split(v0, v1, hw, lw);
                    __nv_bfloat16* ph = (which == 0) ? g_q_hi : (which == 1) ? g_k_hi : g_v_hi;
                    __nv_bfloat16* pl = (which == 0) ? g_q_lo : (which == 1) ? g_k_lo : g_v_lo;
                    *(uint32_t*)(ph + dst) = hw;
                    *(uint32_t*)(pl + dst) = lw;
                }
            }
        }
    }
}

// ---------------- weight transpose + bf16 split ------------------------------
__global__ __launch_bounds__(256) void transpose_split(const float* __restrict__ W,
                                                       int K, int N,
                                                       __nv_bfloat16* __restrict__ Th,
                                                       __nv_bfloat16* __restrict__ Tl) {
    __shared__ float tile[32][33];
    int n0 = blockIdx.x * 32, k0 = blockIdx.y * 32;
    int tx = threadIdx.x & 31, ty = threadIdx.x >> 5;
#pragma unroll
    for (int i = 0; i < 32; i += 8)
        tile[ty + i][tx] = W[(size_t)(k0 + ty + i) * N + n0 + tx];
    __syncthreads();
#pragma unroll
    for (int i = 0; i < 32; i += 8) {
        float v = tile[tx][ty + i];
        __nv_bfloat16 hi, lo;
        split_bf16(v, hi, lo);
        size_t o = (size_t)(n0 + ty + i) * K + k0 + tx;
        Th[o] = hi;
        Tl[o] = lo;
    }
}

// ---------------- LayerNorm -> bf16 hi/lo split --------------------------------
__global__ __launch_bounds__(256) void ln_split(const float* __restrict__ in,
                                                const float* __restrict__ w,
                                                const float* __restrict__ bvec,
                                                __nv_bfloat16* __restrict__ oh,
                                                __nv_bfloat16* __restrict__ ol) {
    int row = blockIdx.x;
    const float* r = in + (size_t)row * C_;
    int tid = threadIdx.x;
    float v[4];
    float s = 0.f, ss = 0.f;
#pragma unroll
    for (int i = 0; i < 4; i++) {
        v[i] = r[tid + i * 256];
        s += v[i];
        ss += v[i] * v[i];
    }
#pragma unroll
    for (int o = 16; o; o >>= 1) {
        s  += __shfl_xor_sync(0xffffffffu, s, o);
        ss += __shfl_xor_sync(0xffffffffu, ss, o);
    }
    __shared__ float rs_[8], rss_[8];
    __shared__ float s_mean, s_rstd;
    int warp = tid >> 5, lane = tid & 31;
    if (lane == 0) { rs_[warp] = s; rss_[warp] = ss; }
    __syncthreads();
    if (tid == 0) {
        float ts = 0.f, tss = 0.f;
#pragma unroll
        for (int i = 0; i < 8; i++) { ts += rs_[i]; tss += rss_[i]; }
        float mean = ts * (1.0f / C_);
        float var = tss * (1.0f / C_) - mean * mean;
        s_mean = mean;
        s_rstd = rsqrtf(var + EPS);
    }
    __syncthreads();
    float mean = s_mean, rstd = s_rstd;
#pragma unroll
    for (int i = 0; i < 4; i++) {
        int c = tid + i * 256;
        float o = (v[i] - mean) * rstd * w[c] + bvec[c];
        __nv_bfloat16 hi, lo;
        split_bf16(o, hi, lo);
        oh[(size_t)row * C_ + c] = hi;
        ol[(size_t)row * C_ + c] = lo;
    }
}

// ---------------- HMMA flash attention (causal) --------------------------------
// CTA: 128 q-rows x 64-key tiles, 8 warps, grid (T/128, B*H).
// smem: Qhi 16K | Qlo 16K | 2 x (Khi 8K | Klo 8K | Vhi 8K | Vlo 8K) = 96KB
constexpr int SMEM_FLASH = 98304;

__global__ __launch_bounds__(256, 1) void flash2() {
    extern __shared__ __align__(1024) char smx[];
    const uint32_t sbase = smem_u32(smx);
    const int tid = threadIdx.x, wid = tid >> 5, lane = tid & 31;
    const int qt = blockIdx.x, bh = blockIdx.y;
    const int q0 = qt * 128;
    const size_t hbase = (size_t)bh * (T_ * HS_);

    {
        const __nv_bfloat16* qh = g_q_hi + hbase + (size_t)q0 * 64;
        const __nv_bfloat16* ql = g_q_lo + hbase + (size_t)q0 * 64;
#pragma unroll
        for (int i = 0; i < 4; i++) {
            int u = tid + 256 * i;
            int r = u >> 3, seg = u & 7;
            uint32_t so = (uint32_t)(r * 128 + ((seg * 16) ^ ((r & 7) * 16)));
            cp_async16(sbase + so,         qh + r * 64 + seg * 8);
            cp_async16(sbase + 16384 + so, ql + r * 64 + seg * 8);
        }
        cp_commit();
    }

    auto load_kv = [&](int kt) {
        uint32_t sb = sbase + 32768u + (uint32_t)(kt & 1) * 32768u;
        const size_t kb = hbase + (size_t)kt * 64 * 64;
#pragma unroll
        for (int i = 0; i < 2; i++) {
            int u = tid + 256 * i;
            int r = u >> 3, seg = u & 7;
            uint32_t so = (uint32_t)(r * 128 + ((seg * 16) ^ ((r & 7) * 16)));
            size_t go = kb + r * 64 + seg * 8;
            cp_async16(sb + so,         g_k_hi + go);
            cp_async16(sb + 8192 + so,  g_k_lo + go);
            cp_async16(sb + 16384 + so, g_v_hi + go);
            cp_async16(sb + 24576 + so, g_v_lo + go);
        }
        cp_commit();
    };

    load_kv(0);
    asm volatile("cp.async.wait_group 1;" ::: "memory");
    __syncthreads();

    uint32_t qh[4][4], ql[4][4];
    {
        const int a_mtx = lane >> 3;
        const int a_m = wid * 16 + (a_mtx & 1) * 8 + (lane & 7);
        const int a_kh = (a_mtx >> 1) * 16;
#pragma unroll
        for (int s = 0; s < 4; s++) {
            uint32_t kb = (uint32_t)(s * 32 + a_kh);
            uint32_t off = (uint32_t)(a_m * 128) + (kb ^ (uint32_t)((a_m & 7) * 16));
            ldmatrix_x4(qh[s], sbase + off);
            ldmatrix_x4(ql[s], sbase + 16384 + off);
        }
    }

    const int ktmax = qt * 2 + 1;
    float m0 = -1e30f, m1 = -1e30f, l0 = 0.f, l1 = 0.f;
    float acc[8][4];
#pragma unroll
    for (int i = 0; i < 8; i++)
#pragma unroll
        for (int j = 0; j < 4; j++) acc[i][j] = 0.f;

    const int b_mtx = lane >> 3;
    const int kn_in = (b_mtx >> 1) * 8 + (lane & 7);
    const int kk_h = (b_mtx & 1) * 16;
    const int v_row_in = (b_mtx & 1) * 8 + (lane & 7);
    const int v_col = (b_mtx >> 1) * 16;
    const int row0 = q0 + wid * 16 + (lane >> 2);

    for (int kt = 0; kt <= ktmax; kt++) {
        if (kt < ktmax) {
            load_kv(kt + 1);
            asm volatile("cp.async.wait_group 1;" ::: "memory");
        } else {
            asm volatile("cp.async.wait_group 0;" ::: "memory");
        }
        __syncthreads();
        const uint32_t sb = sbase + 32768u + (uint32_t)(kt & 1) * 32768u;

        float S[8][4];
#pragma unroll
        for (int i = 0; i < 8; i++)
#pragma unroll
            for (int j = 0; j < 4; j++) S[i][j] = 0.f;
#pragma unroll
        for (int s = 0; s < 4; s++) {
            uint32_t kf[4][4];
#pragma unroll
            for (int g = 0; g < 4; g++) {
                int n = g * 16 + kn_in;
                uint32_t kb = (uint32_t)(s * 32 + kk_h);
                uint32_t off = (uint32_t)(n * 128) + (kb ^ (uint32_t)((n & 7) * 16));
                ldmatrix_x4(kf[g], sb + off);
            }
#pragma unroll
            for (int nt = 0; nt < 8; nt++) {
                mma_bf16(S[nt], qh[s], &kf[nt >> 1][(nt & 1) * 2]);
                mma_bf16(S[nt], ql[s], &kf[nt >> 1][(nt & 1) * 2]);
            }
#pragma unroll
            for (int g = 0; g < 4; g++) {
                int n = g * 16 + kn_in;
                uint32_t kb = (uint32_t)(s * 32 + kk_h);
                uint32_t off = (uint32_t)(n * 128) + (kb ^ (uint32_t)((n & 7) * 16));
                ldmatrix_x4(kf[g], sb + 8192 + off);
            }
#pragma unroll
            for (int nt = 0; nt < 8; nt++)
                mma_bf16(S[nt], qh[s], &kf[nt >> 1][(nt & 1) * 2]);
        }

        if (kt >= 2 * qt) {
#pragma unroll
            for (int nt = 0; nt < 8; nt++) {
                int col = kt * 64 + nt * 8 + (lane & 3) * 2;
                if (col > row0)          S[nt][0] = -1e30f;
                if (col + 1 > row0)      S[nt][1] = -1e30f;
                if (col > row0 + 8)      S[nt][2] = -1e30f;
                if (col + 1 > row0 + 8)  S[nt][3] = -1e30f;
            }
        }

        float mx0 = -1e30f, mx1 = -1e30f;
#pragma unroll
        for (int nt = 0; nt < 8; nt++) {
            mx0 = fmaxf(mx0, fmaxf(S[nt][0], S[nt][1]));
            mx1 = fmaxf(mx1, fmaxf(S[nt][2], S[nt][3]));
        }
        mx0 = fmaxf(mx0, __shfl_xor_sync(0xffffffffu, mx0, 1));
        mx0 = fmaxf(mx0, __shfl_xor_sync(0xffffffffu, mx0, 2));
        mx1 = fmaxf(mx1, __shfl_xor_sync(0xffffffffu, mx1, 1));
        mx1 = fmaxf(mx1, __shfl_xor_sync(0xffffffffu, mx1, 2));
        float mn0 = fmaxf(m0, mx0), mn1 = fmaxf(m1, mx1);
        float al0 = fast_exp(m0 - mn0), al1 = fast_exp(m1 - mn1);
        m0 = mn0; m1 = mn1;
        float sm0 = 0.f, sm1 = 0.f;
#pragma unroll
        for (int nt = 0; nt < 8; nt++) {
            S[nt][0] = fast_exp(S[nt][0] - mn0);
            S[nt][1] = fast_exp(S[nt][1] - mn0);
            S[nt][2] = fast_exp(S[nt][2] - mn1);
            S[nt][3] = fast_exp(S[nt][3] - mn1);
            sm0 += S[nt][0] + S[nt][1];
            sm1 += S[nt][2] + S[nt][3];
        }
        sm0 += __shfl_xor_sync(0xffffffffu, sm0, 1);
        sm0 += __shfl_xor_sync(0xffffffffu, sm0, 2);
        sm1 += __shfl_xor_sync(0xffffffffu, sm1, 1);
        sm1 += __shfl_xor_sync(0xffffffffu, sm1, 2);
        l0 = l0 * al0 + sm0;
        l1 = l1 * al1 + sm1;
#pragma unroll
        for (int nt = 0; nt < 8; nt++) {
            acc[nt][0] *= al0; acc[nt][1] *= al0;
            acc[nt][2] *= al1; acc[nt][3] *= al1;
        }

        uint32_t ph[4][4], pl[4][4];
#pragma unroll
        for (int s = 0; s < 4; s++) {
            pack2_split(S[2 * s][0],     S[2 * s][1],     ph[s][0], pl[s][0]);
            pack2_split(S[2 * s][2],     S[2 * s][3],     ph[s][1], pl[s][1]);
            pack2_split(S[2 * s + 1][0], S[2 * s + 1][1], ph[s][2], pl[s][2]);
            pack2_split(S[2 * s + 1][2], S[2 * s + 1][3], ph[s][3], pl[s][3]);
        }

#pragma unroll
        for (int s = 0; s < 4; s++) {
            uint32_t vf[4][4];
#pragma unroll
            for (int g = 0; g < 4; g++) {
                int row = s * 16 + v_row_in;
                uint32_t cb = (uint32_t)(g * 32 + v_col);
                uint32_t off = (uint32_t)(row * 128) + (cb ^ (uint32_t)((row & 7) * 16));
                ldmatrix_x4_trans(vf[g], sb + 16384 + off);
            }
#pragma unroll
            for (int nt = 0; nt < 8; nt++) {
                mma_bf16(acc[nt], ph[s], &vf[nt >> 1][(nt & 1) * 2]);
                mma_bf16(acc[nt], pl[s], &vf[nt >> 1][(nt & 1) * 2]);
            }
#pragma unroll
            for (int g = 0; g < 4; g++) {
                int row = s * 16 + v_row_in;
                uint32_t cb = (uint32_t)(g * 32 + v_col);
                uint32_t off = (uint32_t)(row * 128) + (cb ^ (uint32_t)((row & 7) * 16));
                ldmatrix_x4_trans(vf[g], sb + 24576 + off);
            }
#pragma unroll
            for (int nt = 0; nt < 8; nt++)
                mma_bf16(acc[nt], ph[s], &vf[nt >> 1][(nt & 1) * 2]);
        }
        __syncthreads();
    }

    float inv0 = 1.f / l0, inv1 = 1.f / l1;
    int b = bh >> 4, h = bh & 15;
#pragma unroll
    for (int nt = 0; nt < 8; nt++) {
        int d = nt * 8 + (lane & 3) * 2;
        size_t o0 = (size_t)(b * 2048 + row0) * 1024 + h * 64 + d;
        uint32_t hw, lw;
        pack2_split(acc[nt][0] * inv0, acc[nt][1] * inv0, hw, lw);
        *(uint32_t*)(g_y_hi + o0) = hw;
        *(uint32_t*)(g_y_lo + o0) = lw;
        size_t o1 = o0 + 8 * 1024;
        pack2_split(acc[nt][2] * inv1, acc[nt][3] * inv1, hw, lw);
        *(uint32_t*)(g_y_hi + o1) = hw;
        *(uint32_t*)(g_y_lo + o1) = lw;
    }
}

// ---------------- KV quantization ---------------------------------------------
__global__ void init_absmax_kernel() {
    g_absmax[0] = 0u;
    g_absmax[1] = 0u;
}

__global__ __launch_bounds__(256) void absmax_kernel() {
    float mk = 0.f, mv = 0.f;
    int N = BT * C_;
    for (int i = blockIdx.x * blockDim.x + threadIdx.x; i < N;
         i += gridDim.x * blockDim.x) {
        float kk = __bfloat162float(g_k_hi[i]) + __bfloat162float(g_k_lo[i]);
        float vv = __bfloat162float(g_v_hi[i]) + __bfloat162float(g_v_lo[i]);
        mk = fmaxf(mk, fabsf(kk));
        mv = fmaxf(mv, fabsf(vv));
    }
#pragma unroll
    for (int o = 16; o; o >>= 1) {
        mk = fmaxf(mk, __shfl_xor_sync(0xffffffffu, mk, o));
        mv = fmaxf(mv, __shfl_xor_sync(0xffffffffu, mv, o));
    }
    __shared__ float sk_[8], sv_[8];
    int warp = threadIdx.x >> 5, lane = threadIdx.x & 31;
    if (lane == 0) { sk_[warp] = mk; sv_[warp] = mv; }
    __syncthreads();
    if (threadIdx.x == 0) {
        float tk = 0.f, tv = 0.f;
#pragma unroll
        for (int i = 0; i < 8; i++) {
            tk = fmaxf(tk, sk_[i]);
            tv = fmaxf(tv, sv_[i]);
        }
        atomicMax(&g_absmax[0], __float_as_uint(tk));
        atomicMax(&g_absmax[1], __float_as_uint(tv));
    }
}

__global__ __launch_bounds__(256) void quant_kernel(float* __restrict__ out) {
    float ak = __uint_as_float(g_absmax[0]);
    float av = __uint_as_float(g_absmax[1]);
    float sk = ak > 0.f ? ak * (1.f / 127.f) : 1.f;
    float sv = av > 0.f ? av * (1.f / 127.f) : 1.f;
    float rk = 1.f / sk, rv = 1.f / sv;
    int N = BT * C_;
    for (int idx = blockIdx.x * blockDim.x + threadIdx.x; idx < N;
         idx += gridDim.x * blockDim.x) {
        float kk = __bfloat162float(g_k_hi[idx]) + __bfloat162float(g_k_lo[idx]);
        float vv = __bfloat162float(g_v_hi[idx]) + __bfloat162float(g_v_lo[idx]);
        out[OFF_KQ + idx] = fminf(fmaxf(rintf(kk * rk), -127.f), 127.f);
        out[OFF_VQ + idx] = fminf(fmaxf(rintf(vv * rv), -127.f), 127.f);
    }
    if (blockIdx.x == 0 && threadIdx.x == 0) {
        out[OFF_KS] = sk;
        out[OFF_VS] = sv;
    }
}

// ---------------- launch --------------------------------------------------------
extern "C" void kernel_launch(void* const* d_in, const int* in_sizes, int n_in,
                              void* d_out, int out_size) {
    const float* x     = (const float*)d_in[0];
    const float* ln1_w = (const float*)d_in[1];
    const float* ln1_b = (const float*)d_in[2];
    const float* W_qkv = (const float*)d_in[3];
    const float* b_qkv = (const float*)d_in[4];
    const float* W_o   = (const float*)d_in[5];
    const float* b_o   = (const float*)d_in[6];
    const float* ln2_w = (const float*)d_in[7];
    const float* ln2_b = (const float*)d_in[8];
    const float* W_fc  = (const float*)d_in[9];
    const float* b_fc  = (const float*)d_in[10];
    const float* W_pr  = (const float*)d_in[11];
    const float* b_pr  = (const float*)d_in[12];
    float* out = (float*)d_out;

    float *x1;
    __nv_bfloat16 *a_hi, *a_lo, *y_hi, *y_lo, *fc_hi, *fc_lo;
    __nv_bfloat16 *wqkv_hi, *wqkv_lo, *wo_hi, *wo_lo, *wfc_hi, *wfc_lo, *wpr_hi, *wpr_lo;
    cudaGetSymbolAddress((void**)&x1, g_x1);
    cudaGetSymbolAddress((void**)&a_hi, g_a_hi);
    cudaGetSymbolAddress((void**)&a_lo, g_a_lo);
    cudaGetSymbolAddress((void**)&y_hi, g_y_hi);
    cudaGetSymbolAddress((void**)&y_lo, g_y_lo);
    cudaGetSymbolAddress((void**)&fc_hi, g_fc_hi);
    cudaGetSymbolAddress((void**)&fc_lo, g_fc_lo);
    cudaGetSymbolAddress((void**)&wqkv_hi, g_wqkv_hi);
    cudaGetSymbolAddress((void**)&wqkv_lo, g_wqkv_lo);
    cudaGetSymbolAddress((void**)&wo_hi, g_wo_hi);
    cudaGetSymbolAddress((void**)&wo_lo, g_wo_lo);
    cudaGetSymbolAddress((void**)&wfc_hi, g_wfc_hi);
    cudaGetSymbolAddress((void**)&wfc_lo, g_wfc_lo);
    cudaGetSymbolAddress((void**)&wpr_hi, g_wpr_hi);
    cudaGetSymbolAddress((void**)&wpr_lo, g_wpr_lo);

    cudaFuncSetAttribute(flash2,
                         cudaFuncAttributeMaxDynamicSharedMemorySize, SMEM_FLASH);
    cudaFuncSetAttribute(mma_gemm<1>,
                         cudaFuncAttributeMaxDynamicSharedMemorySize, SMEM_GEMM);
    cudaFuncSetAttribute(mma_gemm<2>,
                         cudaFuncAttributeMaxDynamicSharedMemorySize, SMEM_GEMM);
    cudaFuncSetAttribute(mma_gemm<3>,
                         cudaFuncAttributeMaxDynamicSharedMemorySize, SMEM_GEMM);

    dim3 tb(256);
    // weight prep: W[K,N] -> W^T[N,K] bf16 hi/lo
    transpose_split<<<dim3(C3 / 32, C_ / 32), tb>>>(W_qkv, C_, C3, wqkv_hi, wqkv_lo);
    transpose_split<<<dim3(C_ / 32, C_ / 32), tb>>>(W_o, C_, C_, wo_hi, wo_lo);
    transpose_split<<<dim3(4 * C_ / 32, C_ / 32), tb>>>(W_fc, C_, 4 * C_, wfc_hi, wfc_lo);
    transpose_split<<<dim3(C_ / 32, 4 * C_ / 32), tb>>>(W_pr, 4 * C_, C_, wpr_hi, wpr_lo);

    // 1. LN1 -> bf16 split
    ln_split<<<BT, 256>>>(x, ln1_w, ln1_b, a_hi, a_lo);
    // 2. QKV GEMM -> scatter q/k/v hi/lo [B,H,T,HS] (q scaled 0.125)
    mma_gemm<3><<<dim3(C3 / 128, BT / 128), 256, SMEM_GEMM>>>(
        a_hi, a_lo, wqkv_hi, wqkv_lo, b_qkv, nullptr, nullptr, nullptr, nullptr,
        BT, C3, C_);
    // 3. HMMA causal flash attention -> y hi/lo
    flash2<<<dim3(T_ / 128, B_ * H_), 256, SMEM_FLASH>>>();
    // 4. proj + residual(x) -> x1
    mma_gemm<2><<<dim3(C_ / 128, BT / 128), 256, SMEM_GEMM>>>(
        y_hi, y_lo, wo_hi, wo_lo, b_o, x, x1, nullptr, nullptr,
        BT, C_, C_);
    // 5. LN2 -> bf16 split
    ln_split<<<BT, 256>>>(x1, ln2_w, ln2_b, a_hi, a_lo);
    // 6. FC + GELU -> fc hi/lo bf16
    mma_gemm<1><<<dim3(4 * C_ / 128, BT / 128), 256, SMEM_GEMM>>>(
        a_hi, a_lo, wfc_hi, wfc_lo, b_fc, nullptr, nullptr, fc_hi, fc_lo,
        BT, 4 * C_, C_);
    // 7. proj + residual(x1) -> out
    mma_gemm<2><<<dim3(C_ / 128, BT / 128), 256, SMEM_GEMM>>>(
        fc_hi, fc_lo, wpr_hi, wpr_lo, b_pr, x1, out + OFF_X, nullptr, nullptr,
        BT, C_, 4 * C_);
    // 8-10. KV int8 quantization
    init_absmax_kernel<<<1, 1>>>();
    absmax_kernel<<<2048, 256>>>();
    quant_kernel<<<4096, 256>>>(out);
}

// round 6
// speedup vs baseline: 5.2915x; 1.5451x over previous
#include <cuda_runtime.h>
#include <cuda_bf16.h>
#include <cuda_fp16.h>
#include <cstdint>
#include <math.h>

// Problem constants
constexpr int B_ = 4, T_ = 2048, C_ = 1024, H_ = 16, HS_ = 64;
constexpr int BT = B_ * T_;            // 8192 rows
constexpr int C3 = 3 * C_;             // 3072
constexpr float EPS = 1e-5f;

// Output layout (concatenated float32):
constexpr int OFF_X  = 0;
constexpr int OFF_KQ = BT * C_;
constexpr int OFF_KS = OFF_KQ + BT * C_;
constexpr int OFF_VQ = OFF_KS + 1;
constexpr int OFF_VS = OFF_VQ + BT * C_;

// ---------------- scratch (device globals) -----------------------------------
__device__ float g_x1 [BT * C_];
__device__ __nv_bfloat16 g_a_hi [BT * C_], g_a_lo [BT * C_];   // LN1 out (QKV input)
// q/k/v in [B,H,T,HS] layout, hi/lo bf16 split. q pre-scaled by 0.125.
__device__ __nv_bfloat16 g_q_hi[BT * C_], g_q_lo[BT * C_];
__device__ __nv_bfloat16 g_k_hi[BT * C_], g_k_lo[BT * C_];
__device__ __nv_bfloat16 g_v_hi[BT * C_], g_v_lo[BT * C_];
__device__ __nv_bfloat16 g_wqkv_hi[C3 * C_], g_wqkv_lo[C3 * C_];
// fp16 path (attention-out / MLP)
__device__ __half g_y_h [BT * C_];          // attention out
__device__ __half g_h2  [BT * C_];          // LN2 out
__device__ __half g_fc_h[BT * 4 * C_];      // gelu(fc) out
__device__ __half g_wo_h [C_ * C_];
__device__ __half g_wfc_h[4 * C_ * C_];
__device__ __half g_wpr_h[C_ * 4 * C_];
__device__ unsigned g_absmax[2];

// ---------------- helpers -------------------------------------------------
__device__ __forceinline__ uint32_t smem_u32(const void* p) {
    return (uint32_t)__cvta_generic_to_shared(p);
}
__device__ __forceinline__ void cp_async16(uint32_t dst, const void* src) {
    asm volatile("cp.async.cg.shared.global [%0], [%1], 16;"
                 :: "r"(dst), "l"(src) : "memory");
}
__device__ __forceinline__ void cp_commit() {
    asm volatile("cp.async.commit_group;" ::: "memory");
}
__device__ __forceinline__ void ldmatrix_x4(uint32_t* r, uint32_t addr) {
    asm volatile("ldmatrix.sync.aligned.m8n8.x4.shared.b16 {%0,%1,%2,%3}, [%4];"
                 : "=r"(r[0]), "=r"(r[1]), "=r"(r[2]), "=r"(r[3]) : "r"(addr));
}
__device__ __forceinline__ void ldmatrix_x4_trans(uint32_t* r, uint32_t addr) {
    asm volatile("ldmatrix.sync.aligned.m8n8.x4.trans.shared.b16 {%0,%1,%2,%3}, [%4];"
                 : "=r"(r[0]), "=r"(r[1]), "=r"(r[2]), "=r"(r[3]) : "r"(addr));
}
__device__ __forceinline__ void mma_bf16(float* d, const uint32_t* a, const uint32_t* b) {
    asm volatile("mma.sync.aligned.m16n8k16.row.col.f32.bf16.bf16.f32 "
                 "{%0,%1,%2,%3},{%4,%5,%6,%7},{%8,%9},{%0,%1,%2,%3};"
                 : "+f"(d[0]), "+f"(d[1]), "+f"(d[2]), "+f"(d[3])
                 : "r"(a[0]), "r"(a[1]), "r"(a[2]), "r"(a[3]),
                   "r"(b[0]), "r"(b[1]));
}
__device__ __forceinline__ void mma_f16(float* d, const uint32_t* a, const uint32_t* b) {
    asm volatile("mma.sync.aligned.m16n8k16.row.col.f32.f16.f16.f32 "
                 "{%0,%1,%2,%3},{%4,%5,%6,%7},{%8,%9},{%0,%1,%2,%3};"
                 : "+f"(d[0]), "+f"(d[1]), "+f"(d[2]), "+f"(d[3])
                 : "r"(a[0]), "r"(a[1]), "r"(a[2]), "r"(a[3]),
                   "r"(b[0]), "r"(b[1]));
}
__device__ __forceinline__ void split_bf16(float v, __nv_bfloat16& hi, __nv_bfloat16& lo) {
    hi = __float2bfloat16(v);
    lo = __float2bfloat16(v - __bfloat162float(hi));
}
__device__ __forceinline__ void pack2_split(float x, float y, uint32_t& hi, uint32_t& lo) {
    __nv_bfloat16 hx, lx, hy, ly;
    split_bf16(x, hx, lx);
    split_bf16(y, hy, ly);
    __nv_bfloat162 h; h.x = hx; h.y = hy;
    __nv_bfloat162 l; l.x = lx; l.y = ly;
    hi = *(uint32_t*)&h;
    lo = *(uint32_t*)&l;
}
// exp(x), FMA-pipe only (no MUFU).
__device__ __forceinline__ float fast_exp(float x) {
    float t = x * 1.4426950408889634f;
    t = fmaxf(t, -126.0f);
    float z = t + 12582912.f;
    int i = __float_as_int(z) - 0x4B400000;
    float f = t - (z - 12582912.f);
    float p = 9.6181291e-3f;
    p = fmaf(p, f, 5.5504109e-2f);
    p = fmaf(p, f, 2.4022651e-1f);
    p = fmaf(p, f, 6.9314718e-1f);
    p = fmaf(p, f, 1.0f);
    return __int_as_float(__float_as_int(p) + (i << 23));
}

// ======== bf16x3 split GEMM (QKV only): scatter epilogue ======================
// CTA 128x128, K-chunk 32 (64B rows), 3-stage, 2 CTAs/SM.
constexpr int GSTAGE = 32768;
constexpr int SMEM_GEMM = 3 * GSTAGE;

__global__ __launch_bounds__(256, 2)
void mma_gemm_qkv(const __nv_bfloat16* __restrict__ Ah, const __nv_bfloat16* __restrict__ Al,
                  const __nv_bfloat16* __restrict__ Bh, const __nv_bfloat16* __restrict__ Bl,
                  const float* __restrict__ bias, int M, int N, int K) {
    extern __shared__ __align__(1024) char smx[];
    const uint32_t sbase = smem_u32(smx);
    const int tid = threadIdx.x;
    const int wid = tid >> 5, lane = tid & 31;
    const int warp_m = wid & 3, warp_n = wid >> 2;
    const int rowC = blockIdx.y * 128, colC = blockIdx.x * 128;
    const int NC = K >> 5;

    float acc[2][8][4];
#pragma unroll
    for (int i = 0; i < 2; i++)
#pragma unroll
        for (int j = 0; j < 8; j++)
#pragma unroll
            for (int q = 0; q < 4; q++) acc[i][j][q] = 0.f;

    const int ld_r = tid >> 2;
    const int ld_seg = tid & 3;

    auto issue = [&](int c) {
        const uint32_t sb = sbase + (uint32_t)(c % 3) * (uint32_t)GSTAGE;
        const int k0 = c << 5;
#pragma unroll
        for (int i = 0; i < 2; i++) {
            int r = ld_r + i * 64;
            uint32_t so = (uint32_t)(r * 64 + ((ld_seg ^ ((r >> 1) & 3)) * 16));
            size_t goA = (size_t)(rowC + r) * K + k0 + ld_seg * 8;
            size_t goB = (size_t)(colC + r) * K + k0 + ld_seg * 8;
            cp_async16(sb + so,          Ah + goA);
            cp_async16(sb + 8192 + so,   Al + goA);
            cp_async16(sb + 16384 + so,  Bh + goB);
            cp_async16(sb + 24576 + so,  Bl + goB);
        }
        cp_commit();
    };

    const int a_mtx = lane >> 3;
    const int a_m_in = (a_mtx & 1) * 8 + (lane & 7);
    const int a_sh = (a_mtx >> 1);
    const int b_n_in = (a_mtx >> 1) * 8 + (lane & 7);
    const int b_sh = (a_mtx & 1);

    issue(0);
    issue(1);
    for (int c = 0; c < NC; c++) {
        if (c + 1 < NC) {
            asm volatile("cp.async.wait_group 1;" ::: "memory");
        } else {
            asm volatile("cp.async.wait_group 0;" ::: "memory");
        }
        __syncthreads();

        const uint32_t sb = sbase + (uint32_t)(c % 3) * (uint32_t)GSTAGE;
#pragma unroll
        for (int s = 0; s < 2; s++) {
            uint32_t aH[2][4], aL[2][4];
#pragma unroll
            for (int mt = 0; mt < 2; mt++) {
                int m = warp_m * 32 + mt * 16 + a_m_in;
                int seg = s * 2 + a_sh;
                uint32_t off = (uint32_t)(m * 64 + ((seg ^ ((m >> 1) & 3)) * 16));
                ldmatrix_x4(aH[mt], sb + off);
                ldmatrix_x4(aL[mt], sb + 8192 + off);
            }
#pragma unroll
            for (int np = 0; np < 4; np++) {
                uint32_t bH[4], bL[4];
                int n = warp_n * 64 + np * 16 + b_n_in;
                int seg = s * 2 + b_sh;
                uint32_t off = (uint32_t)(n * 64 + ((seg ^ ((n >> 1) & 3)) * 16));
                ldmatrix_x4(bH, sb + 16384 + off);
                ldmatrix_x4(bL, sb + 24576 + off);
#pragma unroll
                for (int mt = 0; mt < 2; mt++)
#pragma unroll
                    for (int hf = 0; hf < 2; hf++) {
                        float* d = acc[mt][np * 2 + hf];
                        mma_bf16(d, aH[mt], &bH[hf * 2]);
                        mma_bf16(d, aH[mt], &bL[hf * 2]);
                        mma_bf16(d, aL[mt], &bH[hf * 2]);
                    }
            }
        }
        if (c + 2 < NC) issue(c + 2);
        __syncthreads();
    }

    // epilogue: scatter q/k/v as hi/lo bf16 in [B,H,T,HS]
    const int er = lane >> 2;
    const int ec = (lane & 3) * 2;
#pragma unroll
    for (int mt = 0; mt < 2; mt++) {
#pragma unroll
        for (int nt = 0; nt < 8; nt++) {
            int n = colC + warp_n * 64 + nt * 8 + ec;
            float b0 = bias[n], b1 = bias[n + 1];
            int which = n >> 10;
            int h = (n >> 6) & 15, d = n & 63;
            __nv_bfloat16* ph = (which == 0) ? g_q_hi : (which == 1) ? g_k_hi : g_v_hi;
            __nv_bfloat16* pl = (which == 0) ? g_q_lo : (which == 1) ? g_k_lo : g_v_lo;
#pragma unroll
            for (int half = 0; half < 2; half++) {
                int m = rowC + warp_m * 32 + mt * 16 + er + half * 8;
                float v0 = acc[mt][nt][half * 2]     + b0;
                float v1 = acc[mt][nt][half * 2 + 1] + b1;
                int bb = m >> 11, t = m & 2047;
                size_t dst = ((size_t)(bb * 16 + h) * 2048 + t) * 64 + d;
                if (which == 0) { v0 *= 0.125f; v1 *= 0.125f; }
                uint32_t hw, lw;
                pack2_split(v0, v1, hw, lw);
                *(uint32_t*)(ph + dst) = hw;
                *(uint32_t*)(pl + dst) = lw;
            }
        }
    }
}

// ======== fp16 single GEMM (W_o / FC / PR) ====================================
// CTA 128x128, K-chunk 64 (128B rows), 3-stage (A 16K | B 16K), 2 CTAs/SM.
// EPI: 1 = bias+gelu -> fp16; 2 = bias+residual -> f32
constexpr int FSTAGE = 32768;
constexpr int SMEM_GEMM_F = 3 * FSTAGE;

template <int EPI>
__global__ __launch_bounds__(256, 2)
void mma_gemm_f16(const __half* __restrict__ A, const __half* __restrict__ Bm,
                  const float* __restrict__ bias, const float* __restrict__ R,
                  float* __restrict__ Cf, __half* __restrict__ Ch,
                  int M, int N, int K) {
    extern __shared__ __align__(1024) char smx[];
    const uint32_t sbase = smem_u32(smx);
    const int tid = threadIdx.x;
    const int wid = tid >> 5, lane = tid & 31;
    const int warp_m = wid & 3, warp_n = wid >> 2;
    const int rowC = blockIdx.y * 128, colC = blockIdx.x * 128;
    const int NC = K >> 6;

    float acc[2][8][4];
#pragma unroll
    for (int i = 0; i < 2; i++)
#pragma unroll
        for (int j = 0; j < 8; j++)
#pragma unroll
            for (int q = 0; q < 4; q++) acc[i][j][q] = 0.f;

    const int ld_r = tid >> 3;
    const int ld_seg = tid & 7;

    auto issue = [&](int c) {
        const uint32_t sb = sbase + (uint32_t)(c % 3) * (uint32_t)FSTAGE;
        const int k0 = c << 6;
#pragma unroll
        for (int i = 0; i < 4; i++) {
            int r = ld_r + i * 32;
            uint32_t so = (uint32_t)(r * 128 + ((ld_seg * 16) ^ ((r & 7) * 16)));
            cp_async16(sb + so,         A  + (size_t)(rowC + r) * K + k0 + ld_seg * 8);
            cp_async16(sb + 16384 + so, Bm + (size_t)(colC + r) * K + k0 + ld_seg * 8);
        }
        cp_commit();
    };

    const int a_mtx = lane >> 3;
    const int a_m_in = (a_mtx & 1) * 8 + (lane & 7);
    const int a_kh = (a_mtx >> 1) * 16;
    const int b_n_in = (a_mtx >> 1) * 8 + (lane & 7);
    const int b_kh = (a_mtx & 1) * 16;

    issue(0);
    issue(1);
    for (int c = 0; c < NC; c++) {
        if (c + 1 < NC) {
            asm volatile("cp.async.wait_group 1;" ::: "memory");
        } else {
            asm volatile("cp.async.wait_group 0;" ::: "memory");
        }
        __syncthreads();

        const uint32_t sb = sbase + (uint32_t)(c % 3) * (uint32_t)FSTAGE;
#pragma unroll
        for (int s = 0; s < 4; s++) {
            uint32_t aF[2][4];
#pragma unroll
            for (int mt = 0; mt < 2; mt++) {
                int m = warp_m * 32 + mt * 16 + a_m_in;
                uint32_t kb = (uint32_t)(s * 32 + a_kh);
                uint32_t off = (uint32_t)(m * 128) + (kb ^ (uint32_t)((m & 7) * 16));
                ldmatrix_x4(aF[mt], sb + off);
            }
#pragma unroll
            for (int np = 0; np < 4; np++) {
                uint32_t bF[4];
                int n = warp_n * 64 + np * 16 + b_n_in;
                uint32_t kb = (uint32_t)(s * 32 + b_kh);
                uint32_t off = (uint32_t)(n * 128) + (kb ^ (uint32_t)((n & 7) * 16));
                ldmatrix_x4(bF, sb + 16384 + off);
#pragma unroll
                for (int mt = 0; mt < 2; mt++)
#pragma unroll
                    for (int hf = 0; hf < 2; hf++)
                        mma_f16(acc[mt][np * 2 + hf], aF[mt], &bF[hf * 2]);
            }
        }
        if (c + 2 < NC) issue(c + 2);
        __syncthreads();
    }

    const int er = lane >> 2;
    const int ec = (lane & 3) * 2;
#pragma unroll
    for (int mt = 0; mt < 2; mt++) {
#pragma unroll
        for (int nt = 0; nt < 8; nt++) {
            int n = colC + warp_n * 64 + nt * 8 + ec;
            float b0 = bias[n], b1 = bias[n + 1];
#pragma unroll
            for (int half = 0; half < 2; half++) {
                int m = rowC + warp_m * 32 + mt * 16 + er + half * 8;
                float v0 = acc[mt][nt][half * 2]     + b0;
                float v1 = acc[mt][nt][half * 2 + 1] + b1;
                size_t o = (size_t)m * N + n;
                if (EPI == 2) {
                    float2 rv = *(const float2*)(R + o);
                    *(float2*)(Cf + o) = make_float2(v0 + rv.x, v1 + rv.y);
                } else {  // gelu -> fp16
                    float g0 = 0.5f * v0 * (1.f + erff(v0 * 0.70710678118654752f));
                    float g1 = 0.5f * v1 * (1.f + erff(v1 * 0.70710678118654752f));
                    __half2 hv = __floats2half2_rn(g0, g1);
                    *(__half2*)(Ch + o) = hv;
                }
            }
        }
    }
}

// ---------------- weight transpose variants -----------------------------------
__global__ __launch_bounds__(256) void transpose_split(const float* __restrict__ W,
                                                       int K, int N,
                                                       __nv_bfloat16* __restrict__ Th,
                                                       __nv_bfloat16* __restrict__ Tl) {
    __shared__ float tile[32][33];
    int n0 = blockIdx.x * 32, k0 = blockIdx.y * 32;
    int tx = threadIdx.x & 31, ty = threadIdx.x >> 5;
#pragma unroll
    for (int i = 0; i < 32; i += 8)
        tile[ty + i][tx] = W[(size_t)(k0 + ty + i) * N + n0 + tx];
    __syncthreads();
#pragma unroll
    for (int i = 0; i < 32; i += 8) {
        float v = tile[tx][ty + i];
        __nv_bfloat16 hi, lo;
        split_bf16(v, hi, lo);
        size_t o = (size_t)(n0 + ty + i) * K + k0 + tx;
        Th[o] = hi;
        Tl[o] = lo;
    }
}

__global__ __launch_bounds__(256) void transpose_f16(const float* __restrict__ W,
                                                     int K, int N,
                                                     __half* __restrict__ Th) {
    __shared__ float tile[32][33];
    int n0 = blockIdx.x * 32, k0 = blockIdx.y * 32;
    int tx = threadIdx.x & 31, ty = threadIdx.x >> 5;
#pragma unroll
    for (int i = 0; i < 32; i += 8)
        tile[ty + i][tx] = W[(size_t)(k0 + ty + i) * N + n0 + tx];
    __syncthreads();
#pragma unroll
    for (int i = 0; i < 32; i += 8) {
        float v = tile[tx][ty + i];
        Th[(size_t)(n0 + ty + i) * K + k0 + tx] = __float2half(v);
    }
}

// ---------------- LayerNorm variants -------------------------------------------
__global__ __launch_bounds__(256) void ln_split(const float* __restrict__ in,
                                                const float* __restrict__ w,
                                                const float* __restrict__ bvec,
                                                __nv_bfloat16* __restrict__ oh,
                                                __nv_bfloat16* __restrict__ ol) {
    int row = blockIdx.x;
    const float* r = in + (size_t)row * C_;
    int tid = threadIdx.x;
    float v[4];
    float s = 0.f, ss = 0.f;
#pragma unroll
    for (int i = 0; i < 4; i++) {
        v[i] = r[tid + i * 256];
        s += v[i];
        ss += v[i] * v[i];
    }
#pragma unroll
    for (int o = 16; o; o >>= 1) {
        s  += __shfl_xor_sync(0xffffffffu, s, o);
        ss += __shfl_xor_sync(0xffffffffu, ss, o);
    }
    __shared__ float rs_[8], rss_[8];
    __shared__ float s_mean, s_rstd;
    int warp = tid >> 5, lane = tid & 31;
    if (lane == 0) { rs_[warp] = s; rss_[warp] = ss; }
    __syncthreads();
    if (tid == 0) {
        float ts = 0.f, tss = 0.f;
#pragma unroll
        for (int i = 0; i < 8; i++) { ts += rs_[i]; tss += rss_[i]; }
        float mean = ts * (1.0f / C_);
        float var = tss * (1.0f / C_) - mean * mean;
        s_mean = mean;
        s_rstd = rsqrtf(var + EPS);
    }
    __syncthreads();
    float mean = s_mean, rstd = s_rstd;
#pragma unroll
    for (int i = 0; i < 4; i++) {
        int c = tid + i * 256;
        float o = (v[i] - mean) * rstd * w[c] + bvec[c];
        __nv_bfloat16 hi, lo;
        split_bf16(o, hi, lo);
        oh[(size_t)row * C_ + c] = hi;
        ol[(size_t)row * C_ + c] = lo;
    }
}

__global__ __launch_bounds__(256) void ln_f16(const float* __restrict__ in,
                                              const float* __restrict__ w,
                                              const float* __restrict__ bvec,
                                              __half* __restrict__ oh) {
    int row = blockIdx.x;
    const float* r = in + (size_t)row * C_;
    int tid = threadIdx.x;
    float v[4];
    float s = 0.f, ss = 0.f;
#pragma unroll
    for (int i = 0; i < 4; i++) {
        v[i] = r[tid + i * 256];
        s += v[i];
        ss += v[i] * v[i];
    }
#pragma unroll
    for (int o = 16; o; o >>= 1) {
        s  += __shfl_xor_sync(0xffffffffu, s, o);
        ss += __shfl_xor_sync(0xffffffffu, ss, o);
    }
    __shared__ float rs_[8], rss_[8];
    __shared__ float s_mean, s_rstd;
    int warp = tid >> 5, lane = tid & 31;
    if (lane == 0) { rs_[warp] = s; rss_[warp] = ss; }
    __syncthreads();
    if (tid == 0) {
        float ts = 0.f, tss = 0.f;
#pragma unroll
        for (int i = 0; i < 8; i++) { ts += rs_[i]; tss += rss_[i]; }
        float mean = ts * (1.0f / C_);
        float var = tss * (1.0f / C_) - mean * mean;
        s_mean = mean;
        s_rstd = rsqrtf(var + EPS);
    }
    __syncthreads();
    float mean = s_mean, rstd = s_rstd;
#pragma unroll
    for (int i = 0; i < 4; i++) {
        int c = tid + i * 256;
        float o = (v[i] - mean) * rstd * w[c] + bvec[c];
        oh[(size_t)row * C_ + c] = __float2half(o);
    }
}

// ---------------- HMMA flash attention (causal) --------------------------------
constexpr int SMEM_FLASH = 98304;

__global__ __launch_bounds__(256, 1) void flash2() {
    extern __shared__ __align__(1024) char smx[];
    const uint32_t sbase = smem_u32(smx);
    const int tid = threadIdx.x, wid = tid >> 5, lane = tid & 31;
    const int qt = blockIdx.x, bh = blockIdx.y;
    const int q0 = qt * 128;
    const size_t hbase = (size_t)bh * (T_ * HS_);

    {
        const __nv_bfloat16* qh = g_q_hi + hbase + (size_t)q0 * 64;
        const __nv_bfloat16* ql = g_q_lo + hbase + (size_t)q0 * 64;
#pragma unroll
        for (int i = 0; i < 4; i++) {
            int u = tid + 256 * i;
            int r = u >> 3, seg = u & 7;
            uint32_t so = (uint32_t)(r * 128 + ((seg * 16) ^ ((r & 7) * 16)));
            cp_async16(sbase + so,         qh + r * 64 + seg * 8);
            cp_async16(sbase + 16384 + so, ql + r * 64 + seg * 8);
        }
        cp_commit();
    }

    auto load_kv = [&](int kt) {
        uint32_t sb = sbase + 32768u + (uint32_t)(kt & 1) * 32768u;
        const size_t kb = hbase + (size_t)kt * 64 * 64;
#pragma unroll
        for (int i = 0; i < 2; i++) {
            int u = tid + 256 * i;
            int r = u >> 3, seg = u & 7;
            uint32_t so = (uint32_t)(r * 128 + ((seg * 16) ^ ((r & 7) * 16)));
            size_t go = kb + r * 64 + seg * 8;
            cp_async16(sb + so,         g_k_hi + go);
            cp_async16(sb + 8192 + so,  g_k_lo + go);
            cp_async16(sb + 16384 + so, g_v_hi + go);
            cp_async16(sb + 24576 + so, g_v_lo + go);
        }
        cp_commit();
    };

    load_kv(0);
    asm volatile("cp.async.wait_group 1;" ::: "memory");
    __syncthreads();

    uint32_t qh[4][4], ql[4][4];
    {
        const int a_mtx = lane >> 3;
        const int a_m = wid * 16 + (a_mtx & 1) * 8 + (lane & 7);
        const int a_kh = (a_mtx >> 1) * 16;
#pragma unroll
        for (int s = 0; s < 4; s++) {
            uint32_t kb = (uint32_t)(s * 32 + a_kh);
            uint32_t off = (uint32_t)(a_m * 128) + (kb ^ (uint32_t)((a_m & 7) * 16));
            ldmatrix_x4(qh[s], sbase + off);
            ldmatrix_x4(ql[s], sbase + 16384 + off);
        }
    }

    const int ktmax = qt * 2 + 1;
    float m0 = -1e30f, m1 = -1e30f, l0 = 0.f, l1 = 0.f;
    float acc[8][4];
#pragma unroll
    for (int i = 0; i < 8; i++)
#pragma unroll
        for (int j = 0; j < 4; j++) acc[i][j] = 0.f;

    const int b_mtx = lane >> 3;
    const int kn_in = (b_mtx >> 1) * 8 + (lane & 7);
    const int kk_h = (b_mtx & 1) * 16;
    const int v_row_in = (b_mtx & 1) * 8 + (lane & 7);
    const int v_col = (b_mtx >> 1) * 16;
    const int row0 = q0 + wid * 16 + (lane >> 2);

    for (int kt = 0; kt <= ktmax; kt++) {
        if (kt < ktmax) {
            load_kv(kt + 1);
            asm volatile("cp.async.wait_group 1;" ::: "memory");
        } else {
            asm volatile("cp.async.wait_group 0;" ::: "memory");
        }
        __syncthreads();
        const uint32_t sb = sbase + 32768u + (uint32_t)(kt & 1) * 32768u;

        float S[8][4];
#pragma unroll
        for (int i = 0; i < 8; i++)
#pragma unroll
            for (int j = 0; j < 4; j++) S[i][j] = 0.f;
#pragma unroll
        for (int s = 0; s < 4; s++) {
            uint32_t kf[4][4];
#pragma unroll
            for (int g = 0; g < 4; g++) {
                int n = g * 16 + kn_in;
                uint32_t kb = (uint32_t)(s * 32 + kk_h);
                uint32_t off = (uint32_t)(n * 128) + (kb ^ (uint32_t)((n & 7) * 16));
                ldmatrix_x4(kf[g], sb + off);
            }
#pragma unroll
            for (int nt = 0; nt < 8; nt++) {
                mma_bf16(S[nt], qh[s], &kf[nt >> 1][(nt & 1) * 2]);
                mma_bf16(S[nt], ql[s], &kf[nt >> 1][(nt & 1) * 2]);
            }
#pragma unroll
            for (int g = 0; g < 4; g++) {
                int n = g * 16 + kn_in;
                uint32_t kb = (uint32_t)(s * 32 + kk_h);
                uint32_t off = (uint32_t)(n * 128) + (kb ^ (uint32_t)((n & 7) * 16));
                ldmatrix_x4(kf[g], sb + 8192 + off);
            }
#pragma unroll
            for (int nt = 0; nt < 8; nt++)
                mma_bf16(S[nt], qh[s], &kf[nt >> 1][(nt & 1) * 2]);
        }

        if (kt >= 2 * qt) {
#pragma unroll
            for (int nt = 0; nt < 8; nt++) {
                int col = kt * 64 + nt * 8 + (lane & 3) * 2;
                if (col > row0)          S[nt][0] = -1e30f;
                if (col + 1 > row0)      S[nt][1] = -1e30f;
                if (col > row0 + 8)      S[nt][2] = -1e30f;
                if (col + 1 > row0 + 8)  S[nt][3] = -1e30f;
            }
        }

        float mx0 = -1e30f, mx1 = -1e30f;
#pragma unroll
        for (int nt = 0; nt < 8; nt++) {
            mx0 = fmaxf(mx0, fmaxf(S[nt][0], S[nt][1]));
            mx1 = fmaxf(mx1, fmaxf(S[nt][2], S[nt][3]));
        }
        mx0 = fmaxf(mx0, __shfl_xor_sync(0xffffffffu, mx0, 1));
        mx0 = fmaxf(mx0, __shfl_xor_sync(0xffffffffu, mx0, 2));
        mx1 = fmaxf(mx1, __shfl_xor_sync(0xffffffffu, mx1, 1));
        mx1 = fmaxf(mx1, __shfl_xor_sync(0xffffffffu, mx1, 2));
        float mn0 = fmaxf(m0, mx0), mn1 = fmaxf(m1, mx1);
        float al0 = fast_exp(m0 - mn0), al1 = fast_exp(m1 - mn1);
        m0 = mn0; m1 = mn1;
        float sm0 = 0.f, sm1 = 0.f;
#pragma unroll
        for (int nt = 0; nt < 8; nt++) {
            S[nt][0] = fast_exp(S[nt][0] - mn0);
            S[nt][1] = fast_exp(S[nt][1] - mn0);
            S[nt][2] = fast_exp(S[nt][2] - mn1);
            S[nt][3] = fast_exp(S[nt][3] - mn1);
            sm0 += S[nt][0] + S[nt][1];
            sm1 += S[nt][2] + S[nt][3];
        }
        sm0 += __shfl_xor_sync(0xffffffffu, sm0, 1);
        sm0 += __shfl_xor_sync(0xffffffffu, sm0, 2);
        sm1 += __shfl_xor_sync(0xffffffffu, sm1, 1);
        sm1 += __shfl_xor_sync(0xffffffffu, sm1, 2);
        l0 = l0 * al0 + sm0;
        l1 = l1 * al1 + sm1;
#pragma unroll
        for (int nt = 0; nt < 8; nt++) {
            acc[nt][0] *= al0; acc[nt][1] *= al0;
            acc[nt][2] *= al1; acc[nt][3] *= al1;
        }

        uint32_t ph[4][4], pl[4][4];
#pragma unroll
        for (int s = 0; s < 4; s++) {
            pack2_split(S[2 * s][0],     S[2 * s][1],     ph[s][0], pl[s][0]);
            pack2_split(S[2 * s][2],     S[2 * s][3],     ph[s][1], pl[s][1]);
            pack2_split(S[2 * s + 1][0], S[2 * s + 1][1], ph[s][2], pl[s][2]);
            pack2_split(S[2 * s + 1][2], S[2 * s + 1][3], ph[s][3], pl[s][3]);
        }

#pragma unroll
        for (int s = 0; s < 4; s++) {
            uint32_t vf[4][4];
#pragma unroll
            for (int g = 0; g < 4; g++) {
                int row = s * 16 + v_row_in;
                uint32_t cb = (uint32_t)(g * 32 + v_col);
                uint32_t off = (uint32_t)(row * 128) + (cb ^ (uint32_t)((row & 7) * 16));
                ldmatrix_x4_trans(vf[g], sb + 16384 + off);
            }
#pragma unroll
            for (int nt = 0; nt < 8; nt++) {
                mma_bf16(acc[nt], ph[s], &vf[nt >> 1][(nt & 1) * 2]);
                mma_bf16(acc[nt], pl[s], &vf[nt >> 1][(nt & 1) * 2]);
            }
#pragma unroll
            for (int g = 0; g < 4; g++) {
                int row = s * 16 + v_row_in;
                uint32_t cb = (uint32_t)(g * 32 + v_col);
                uint32_t off = (uint32_t)(row * 128) + (cb ^ (uint32_t)((row & 7) * 16));
                ldmatrix_x4_trans(vf[g], sb + 24576 + off);
            }
#pragma unroll
            for (int nt = 0; nt < 8; nt++)
                mma_bf16(acc[nt], ph[s], &vf[nt >> 1][(nt & 1) * 2]);
        }
        __syncthreads();
    }

    float inv0 = 1.f / l0, inv1 = 1.f / l1;
    int b = bh >> 4, h = bh & 15;
#pragma unroll
    for (int nt = 0; nt < 8; nt++) {
        int d = nt * 8 + (lane & 3) * 2;
        size_t o0 = (size_t)(b * 2048 + row0) * 1024 + h * 64 + d;
        *(__half2*)(g_y_h + o0) = __floats2half2_rn(acc[nt][0] * inv0, acc[nt][1] * inv0);
        size_t o1 = o0 + 8 * 1024;
        *(__half2*)(g_y_h + o1) = __floats2half2_rn(acc[nt][2] * inv1, acc[nt][3] * inv1);
    }
}

// ---------------- KV quantization ---------------------------------------------
__global__ void init_absmax_kernel() {
    g_absmax[0] = 0u;
    g_absmax[1] = 0u;
}

__global__ __launch_bounds__(256) void absmax_kernel() {
    float mk = 0.f, mv = 0.f;
    int N = BT * C_;
    for (int i = blockIdx.x * blockDim.x + threadIdx.x; i < N;
         i += gridDim.x * blockDim.x) {
        float kk = __bfloat162float(g_k_hi[i]) + __bfloat162float(g_k_lo[i]);
        float vv = __bfloat162float(g_v_hi[i]) + __bfloat162float(g_v_lo[i]);
        mk = fmaxf(mk, fabsf(kk));
        mv = fmaxf(mv, fabsf(vv));
    }
#pragma unroll
    for (int o = 16; o; o >>= 1) {
        mk = fmaxf(mk, __shfl_xor_sync(0xffffffffu, mk, o));
        mv = fmaxf(mv, __shfl_xor_sync(0xffffffffu, mv, o));
    }
    __shared__ float sk_[8], sv_[8];
    int warp = threadIdx.x >> 5, lane = threadIdx.x & 31;
    if (lane == 0) { sk_[warp] = mk; sv_[warp] = mv; }
    __syncthreads();
    if (threadIdx.x == 0) {
        float tk = 0.f, tv = 0.f;
#pragma unroll
        for (int i = 0; i < 8; i++) {
            tk = fmaxf(tk, sk_[i]);
            tv = fmaxf(tv, sv_[i]);
        }
        atomicMax(&g_absmax[0], __float_as_uint(tk));
        atomicMax(&g_absmax[1], __float_as_uint(tv));
    }
}

__global__ __launch_bounds__(256) void quant_kernel(float* __restrict__ out) {
    float ak = __uint_as_float(g_absmax[0]);
    float av = __uint_as_float(g_absmax[1]);
    float sk = ak > 0.f ? ak * (1.f / 127.f) : 1.f;
    float sv = av > 0.f ? av * (1.f / 127.f) : 1.f;
    float rk = 1.f / sk, rv = 1.f / sv;
    int N = BT * C_;
    for (int idx = blockIdx.x * blockDim.x + threadIdx.x; idx < N;
         idx += gridDim.x * blockDim.x) {
        float kk = __bfloat162float(g_k_hi[idx]) + __bfloat162float(g_k_lo[idx]);
        float vv = __bfloat162float(g_v_hi[idx]) + __bfloat162float(g_v_lo[idx]);
        out[OFF_KQ + idx] = fminf(fmaxf(rintf(kk * rk), -127.f), 127.f);
        out[OFF_VQ + idx] = fminf(fmaxf(rintf(vv * rv), -127.f), 127.f);
    }
    if (blockIdx.x == 0 && threadIdx.x == 0) {
        out[OFF_KS] = sk;
        out[OFF_VS] = sv;
    }
}

// ---------------- launch --------------------------------------------------------
extern "C" void kernel_launch(void* const* d_in, const int* in_sizes, int n_in,
                              void* d_out, int out_size) {
    const float* x     = (const float*)d_in[0];
    const float* ln1_w = (const float*)d_in[1];
    const float* ln1_b = (const float*)d_in[2];
    const float* W_qkv = (const float*)d_in[3];
    const float* b_qkv = (const float*)d_in[4];
    const float* W_o   = (const float*)d_in[5];
    const float* b_o   = (const float*)d_in[6];
    const float* ln2_w = (const float*)d_in[7];
    const float* ln2_b = (const float*)d_in[8];
    const float* W_fc  = (const float*)d_in[9];
    const float* b_fc  = (const float*)d_in[10];
    const float* W_pr  = (const float*)d_in[11];
    const float* b_pr  = (const float*)d_in[12];
    float* out = (float*)d_out;

    float *x1;
    __nv_bfloat16 *a_hi, *a_lo, *wqkv_hi, *wqkv_lo;
    __half *y_h, *h2, *fc_h, *wo_h, *wfc_h, *wpr_h;
    cudaGetSymbolAddress((void**)&x1, g_x1);
    cudaGetSymbolAddress((void**)&a_hi, g_a_hi);
    cudaGetSymbolAddress((void**)&a_lo, g_a_lo);
    cudaGetSymbolAddress((void**)&wqkv_hi, g_wqkv_hi);
    cudaGetSymbolAddress((void**)&wqkv_lo, g_wqkv_lo);
    cudaGetSymbolAddress((void**)&y_h, g_y_h);
    cudaGetSymbolAddress((void**)&h2, g_h2);
    cudaGetSymbolAddress((void**)&fc_h, g_fc_h);
    cudaGetSymbolAddress((void**)&wo_h, g_wo_h);
    cudaGetSymbolAddress((void**)&wfc_h, g_wfc_h);
    cudaGetSymbolAddress((void**)&wpr_h, g_wpr_h);

    cudaFuncSetAttribute(flash2,
                         cudaFuncAttributeMaxDynamicSharedMemorySize, SMEM_FLASH);
    cudaFuncSetAttribute(mma_gemm_qkv,
                         cudaFuncAttributeMaxDynamicSharedMemorySize, SMEM_GEMM);
    cudaFuncSetAttribute(mma_gemm_f16<1>,
                         cudaFuncAttributeMaxDynamicSharedMemorySize, SMEM_GEMM_F);
    cudaFuncSetAttribute(mma_gemm_f16<2>,
                         cudaFuncAttributeMaxDynamicSharedMemorySize, SMEM_GEMM_F);

    dim3 tb(256);
    // weight prep
    transpose_split<<<dim3(C3 / 32, C_ / 32), tb>>>(W_qkv, C_, C3, wqkv_hi, wqkv_lo);
    transpose_f16<<<dim3(C_ / 32, C_ / 32), tb>>>(W_o, C_, C_, wo_h);
    transpose_f16<<<dim3(4 * C_ / 32, C_ / 32), tb>>>(W_fc, C_, 4 * C_, wfc_h);
    transpose_f16<<<dim3(C_ / 32, 4 * C_ / 32), tb>>>(W_pr, 4 * C_, C_, wpr_h);

    // 1. LN1 -> bf16 split
    ln_split<<<BT, 256>>>(x, ln1_w, ln1_b, a_hi, a_lo);
    // 2. QKV GEMM (bf16x3) -> scatter q/k/v hi/lo [B,H,T,HS]
    mma_gemm_qkv<<<dim3(C3 / 128, BT / 128), 256, SMEM_GEMM>>>(
        a_hi, a_lo, wqkv_hi, wqkv_lo, b_qkv, BT, C3, C_);
    // 3. HMMA causal flash attention -> y fp16
    flash2<<<dim3(T_ / 128, B_ * H_), 256, SMEM_FLASH>>>();
    // 4. proj + residual(x) -> x1 (fp16 GEMM)
    mma_gemm_f16<2><<<dim3(C_ / 128, BT / 128), 256, SMEM_GEMM_F>>>(
        y_h, wo_h, b_o, x, x1, nullptr, BT, C_, C_);
    // 5. LN2 -> fp16
    ln_f16<<<BT, 256>>>(x1, ln2_w, ln2_b, h2);
    // 6. FC + GELU -> fp16 (fp16 GEMM)
    mma_gemm_f16<1><<<dim3(4 * C_ / 128, BT / 128), 256, SMEM_GEMM_F>>>(
        h2, wfc_h, b_fc, nullptr, nullptr, fc_h, BT, 4 * C_, C_);
    // 7. proj + residual(x1) -> out (fp16 GEMM)
    mma_gemm_f16<2><<<dim3(C_ / 128, BT / 128), 256, SMEM_GEMM_F>>>(
        fc_h, wpr_h, b_pr, x1, out + OFF_X, nullptr, BT, C_, 4 * C_);
    // 8-10. KV int8 quantization
    init_absmax_kernel<<<1, 1>>>();
    absmax_kernel<<<2048, 256>>>();
    quant_kernel<<<4096, 256>>>(out);
}

// round 7
// speedup vs baseline: 6.1134x; 1.1553x over previous
#include <cuda_runtime.h>
#include <cuda_bf16.h>
#include <cuda_fp16.h>
#include <cstdint>
#include <math.h>

// Problem constants
constexpr int B_ = 4, T_ = 2048, C_ = 1024, H_ = 16, HS_ = 64;
constexpr int BT = B_ * T_;            // 8192 rows
constexpr int C3 = 3 * C_;             // 3072
constexpr float EPS = 1e-5f;

// Output layout (concatenated float32):
constexpr int OFF_X  = 0;
constexpr int OFF_KQ = BT * C_;
constexpr int OFF_KS = OFF_KQ + BT * C_;
constexpr int OFF_VQ = OFF_KS + 1;
constexpr int OFF_VS = OFF_VQ + BT * C_;

// ---------------- scratch (device globals) -----------------------------------
__device__ float g_x1 [BT * C_];
__device__ __nv_bfloat16 g_a_hi [BT * C_], g_a_lo [BT * C_];   // LN1 out
// q/k/v in [B,H,T,HS]. q single bf16 (pre-scaled 0.125); k/v hi/lo split.
__device__ __nv_bfloat16 g_q_hi[BT * C_];
__device__ __nv_bfloat16 g_k_hi[BT * C_], g_k_lo[BT * C_];
__device__ __nv_bfloat16 g_v_hi[BT * C_], g_v_lo[BT * C_];
__device__ __nv_bfloat16 g_wqkv_hi[C3 * C_], g_wqkv_lo[C3 * C_];
// fp16 path (attention-out / MLP)
__device__ __half g_y_h [BT * C_];
__device__ __half g_h2  [BT * C_];
__device__ __half g_fc_h[BT * 4 * C_];
__device__ __half g_wo_h [C_ * C_];
__device__ __half g_wfc_h[4 * C_ * C_];
__device__ __half g_wpr_h[C_ * 4 * C_];
__device__ unsigned g_absmax[2];

// ---------------- helpers -------------------------------------------------
__device__ __forceinline__ uint32_t smem_u32(const void* p) {
    return (uint32_t)__cvta_generic_to_shared(p);
}
__device__ __forceinline__ void cp_async16(uint32_t dst, const void* src) {
    asm volatile("cp.async.cg.shared.global [%0], [%1], 16;"
                 :: "r"(dst), "l"(src) : "memory");
}
__device__ __forceinline__ void cp_commit() {
    asm volatile("cp.async.commit_group;" ::: "memory");
}
__device__ __forceinline__ void ldmatrix_x4(uint32_t* r, uint32_t addr) {
    asm volatile("ldmatrix.sync.aligned.m8n8.x4.shared.b16 {%0,%1,%2,%3}, [%4];"
                 : "=r"(r[0]), "=r"(r[1]), "=r"(r[2]), "=r"(r[3]) : "r"(addr));
}
__device__ __forceinline__ void ldmatrix_x4_trans(uint32_t* r, uint32_t addr) {
    asm volatile("ldmatrix.sync.aligned.m8n8.x4.trans.shared.b16 {%0,%1,%2,%3}, [%4];"
                 : "=r"(r[0]), "=r"(r[1]), "=r"(r[2]), "=r"(r[3]) : "r"(addr));
}
__device__ __forceinline__ void mma_bf16(float* d, const uint32_t* a, const uint32_t* b) {
    asm volatile("mma.sync.aligned.m16n8k16.row.col.f32.bf16.bf16.f32 "
                 "{%0,%1,%2,%3},{%4,%5,%6,%7},{%8,%9},{%0,%1,%2,%3};"
                 : "+f"(d[0]), "+f"(d[1]), "+f"(d[2]), "+f"(d[3])
                 : "r"(a[0]), "r"(a[1]), "r"(a[2]), "r"(a[3]),
                   "r"(b[0]), "r"(b[1]));
}
__device__ __forceinline__ void mma_f16(float* d, const uint32_t* a, const uint32_t* b) {
    asm volatile("mma.sync.aligned.m16n8k16.row.col.f32.f16.f16.f32 "
                 "{%0,%1,%2,%3},{%4,%5,%6,%7},{%8,%9},{%0,%1,%2,%3};"
                 : "+f"(d[0]), "+f"(d[1]), "+f"(d[2]), "+f"(d[3])
                 : "r"(a[0]), "r"(a[1]), "r"(a[2]), "r"(a[3]),
                   "r"(b[0]), "r"(b[1]));
}
__device__ __forceinline__ void split_bf16(float v, __nv_bfloat16& hi, __nv_bfloat16& lo) {
    hi = __float2bfloat16(v);
    lo = __float2bfloat16(v - __bfloat162float(hi));
}
__device__ __forceinline__ void pack2_split(float x, float y, uint32_t& hi, uint32_t& lo) {
    __nv_bfloat16 hx, lx, hy, ly;
    split_bf16(x, hx, lx);
    split_bf16(y, hy, ly);
    __nv_bfloat162 h; h.x = hx; h.y = hy;
    __nv_bfloat162 l; l.x = lx; l.y = ly;
    hi = *(uint32_t*)&h;
    lo = *(uint32_t*)&l;
}
__device__ __forceinline__ uint32_t pack2_bf16(float x, float y) {
    __nv_bfloat162 h;
    h.x = __float2bfloat16(x);
    h.y = __float2bfloat16(y);
    return *(uint32_t*)&h;
}
// exp(x), FMA-pipe only (no MUFU).
__device__ __forceinline__ float fast_exp(float x) {
    float t = x * 1.4426950408889634f;
    t = fmaxf(t, -126.0f);
    float z = t + 12582912.f;
    int i = __float_as_int(z) - 0x4B400000;
    float f = t - (z - 12582912.f);
    float p = 9.6181291e-3f;
    p = fmaf(p, f, 5.5504109e-2f);
    p = fmaf(p, f, 2.4022651e-1f);
    p = fmaf(p, f, 6.9314718e-1f);
    p = fmaf(p, f, 1.0f);
    return __int_as_float(__float_as_int(p) + (i << 23));
}

// ======== QKV GEMM: bf16x3 for k/v column-tiles, single bf16 for q tiles ======
constexpr int GSTAGE = 32768;
constexpr int SMEM_GEMM = 3 * GSTAGE;

__global__ __launch_bounds__(256, 2)
void mma_gemm_qkv(const __nv_bfloat16* __restrict__ Ah, const __nv_bfloat16* __restrict__ Al,
                  const __nv_bfloat16* __restrict__ Bh, const __nv_bfloat16* __restrict__ Bl,
                  const float* __restrict__ bias, int M, int N, int K) {
    extern __shared__ __align__(1024) char smx[];
    const uint32_t sbase = smem_u32(smx);
    const int tid = threadIdx.x;
    const int wid = tid >> 5, lane = tid & 31;
    const int warp_m = wid & 3, warp_n = wid >> 2;
    const int rowC = blockIdx.y * 128, colC = blockIdx.x * 128;
    const bool qtile = (colC < 1024);   // whole CTA column range is q
    const int NC = K >> 5;

    float acc[2][8][4];
#pragma unroll
    for (int i = 0; i < 2; i++)
#pragma unroll
        for (int j = 0; j < 8; j++)
#pragma unroll
            for (int q = 0; q < 4; q++) acc[i][j][q] = 0.f;

    const int ld_r = tid >> 2;
    const int ld_seg = tid & 3;

    auto issue = [&](int c) {
        const uint32_t sb = sbase + (uint32_t)(c % 3) * (uint32_t)GSTAGE;
        const int k0 = c << 5;
#pragma unroll
        for (int i = 0; i < 2; i++) {
            int r = ld_r + i * 64;
            uint32_t so = (uint32_t)(r * 64 + ((ld_seg ^ ((r >> 1) & 3)) * 16));
            size_t goA = (size_t)(rowC + r) * K + k0 + ld_seg * 8;
            size_t goB = (size_t)(colC + r) * K + k0 + ld_seg * 8;
            cp_async16(sb + so,          Ah + goA);
            cp_async16(sb + 16384 + so,  Bh + goB);
            if (!qtile) {
                cp_async16(sb + 8192 + so,   Al + goA);
                cp_async16(sb + 24576 + so,  Bl + goB);
            }
        }
        cp_commit();
    };

    const int a_mtx = lane >> 3;
    const int a_m_in = (a_mtx & 1) * 8 + (lane & 7);
    const int a_sh = (a_mtx >> 1);
    const int b_n_in = (a_mtx >> 1) * 8 + (lane & 7);
    const int b_sh = (a_mtx & 1);

    issue(0);
    issue(1);
    for (int c = 0; c < NC; c++) {
        if (c + 1 < NC) {
            asm volatile("cp.async.wait_group 1;" ::: "memory");
        } else {
            asm volatile("cp.async.wait_group 0;" ::: "memory");
        }
        __syncthreads();

        const uint32_t sb = sbase + (uint32_t)(c % 3) * (uint32_t)GSTAGE;
#pragma unroll
        for (int s = 0; s < 2; s++) {
            uint32_t aH[2][4], aL[2][4];
#pragma unroll
            for (int mt = 0; mt < 2; mt++) {
                int m = warp_m * 32 + mt * 16 + a_m_in;
                int seg = s * 2 + a_sh;
                uint32_t off = (uint32_t)(m * 64 + ((seg ^ ((m >> 1) & 3)) * 16));
                ldmatrix_x4(aH[mt], sb + off);
                if (!qtile) ldmatrix_x4(aL[mt], sb + 8192 + off);
            }
#pragma unroll
            for (int np = 0; np < 4; np++) {
                uint32_t bH[4], bL[4];
                int n = warp_n * 64 + np * 16 + b_n_in;
                int seg = s * 2 + b_sh;
                uint32_t off = (uint32_t)(n * 64 + ((seg ^ ((n >> 1) & 3)) * 16));
                ldmatrix_x4(bH, sb + 16384 + off);
                if (!qtile) ldmatrix_x4(bL, sb + 24576 + off);
#pragma unroll
                for (int mt = 0; mt < 2; mt++)
#pragma unroll
                    for (int hf = 0; hf < 2; hf++) {
                        float* d = acc[mt][np * 2 + hf];
                        mma_bf16(d, aH[mt], &bH[hf * 2]);
                        if (!qtile) {
                            mma_bf16(d, aH[mt], &bL[hf * 2]);
                            mma_bf16(d, aL[mt], &bH[hf * 2]);
                        }
                    }
            }
        }
        if (c + 2 < NC) issue(c + 2);
        __syncthreads();
    }

    // epilogue: scatter q (hi only) / k / v (hi+lo) into [B,H,T,HS]
    const int er = lane >> 2;
    const int ec = (lane & 3) * 2;
#pragma unroll
    for (int mt = 0; mt < 2; mt++) {
#pragma unroll
        for (int nt = 0; nt < 8; nt++) {
            int n = colC + warp_n * 64 + nt * 8 + ec;
            float b0 = bias[n], b1 = bias[n + 1];
            int which = n >> 10;
            int h = (n >> 6) & 15, d = n & 63;
#pragma unroll
            for (int half = 0; half < 2; half++) {
                int m = rowC + warp_m * 32 + mt * 16 + er + half * 8;
                float v0 = acc[mt][nt][half * 2]     + b0;
                float v1 = acc[mt][nt][half * 2 + 1] + b1;
                int bb = m >> 11, t = m & 2047;
                size_t dst = ((size_t)(bb * 16 + h) * 2048 + t) * 64 + d;
                if (which == 0) {
                    *(uint32_t*)(g_q_hi + dst) = pack2_bf16(v0 * 0.125f, v1 * 0.125f);
                } else {
                    __nv_bfloat16* ph = (which == 1) ? g_k_hi : g_v_hi;
                    __nv_bfloat16* pl = (which == 1) ? g_k_lo : g_v_lo;
                    uint32_t hw, lw;
                    pack2_split(v0, v1, hw, lw);
                    *(uint32_t*)(ph + dst) = hw;
                    *(uint32_t*)(pl + dst) = lw;
                }
            }
        }
    }
}

// ======== fp16 single GEMM (W_o / FC / PR) ====================================
constexpr int FSTAGE = 32768;
constexpr int SMEM_GEMM_F = 3 * FSTAGE;

template <int EPI>
__global__ __launch_bounds__(256, 2)
void mma_gemm_f16(const __half* __restrict__ A, const __half* __restrict__ Bm,
                  const float* __restrict__ bias, const float* __restrict__ R,
                  float* __restrict__ Cf, __half* __restrict__ Ch,
                  int M, int N, int K) {
    extern __shared__ __align__(1024) char smx[];
    const uint32_t sbase = smem_u32(smx);
    const int tid = threadIdx.x;
    const int wid = tid >> 5, lane = tid & 31;
    const int warp_m = wid & 3, warp_n = wid >> 2;
    const int rowC = blockIdx.y * 128, colC = blockIdx.x * 128;
    const int NC = K >> 6;

    float acc[2][8][4];
#pragma unroll
    for (int i = 0; i < 2; i++)
#pragma unroll
        for (int j = 0; j < 8; j++)
#pragma unroll
            for (int q = 0; q < 4; q++) acc[i][j][q] = 0.f;

    const int ld_r = tid >> 3;
    const int ld_seg = tid & 7;

    auto issue = [&](int c) {
        const uint32_t sb = sbase + (uint32_t)(c % 3) * (uint32_t)FSTAGE;
        const int k0 = c << 6;
#pragma unroll
        for (int i = 0; i < 4; i++) {
            int r = ld_r + i * 32;
            uint32_t so = (uint32_t)(r * 128 + ((ld_seg * 16) ^ ((r & 7) * 16)));
            cp_async16(sb + so,         A  + (size_t)(rowC + r) * K + k0 + ld_seg * 8);
            cp_async16(sb + 16384 + so, Bm + (size_t)(colC + r) * K + k0 + ld_seg * 8);
        }
        cp_commit();
    };

    const int a_mtx = lane >> 3;
    const int a_m_in = (a_mtx & 1) * 8 + (lane & 7);
    const int a_kh = (a_mtx >> 1) * 16;
    const int b_n_in = (a_mtx >> 1) * 8 + (lane & 7);
    const int b_kh = (a_mtx & 1) * 16;

    issue(0);
    issue(1);
    for (int c = 0; c < NC; c++) {
        if (c + 1 < NC) {
            asm volatile("cp.async.wait_group 1;" ::: "memory");
        } else {
            asm volatile("cp.async.wait_group 0;" ::: "memory");
        }
        __syncthreads();

        const uint32_t sb = sbase + (uint32_t)(c % 3) * (uint32_t)FSTAGE;
#pragma unroll
        for (int s = 0; s < 4; s++) {
            uint32_t aF[2][4];
#pragma unroll
            for (int mt = 0; mt < 2; mt++) {
                int m = warp_m * 32 + mt * 16 + a_m_in;
                uint32_t kb = (uint32_t)(s * 32 + a_kh);
                uint32_t off = (uint32_t)(m * 128) + (kb ^ (uint32_t)((m & 7) * 16));
                ldmatrix_x4(aF[mt], sb + off);
            }
#pragma unroll
            for (int np = 0; np < 4; np++) {
                uint32_t bF[4];
                int n = warp_n * 64 + np * 16 + b_n_in;
                uint32_t kb = (uint32_t)(s * 32 + b_kh);
                uint32_t off = (uint32_t)(n * 128) + (kb ^ (uint32_t)((n & 7) * 16));
                ldmatrix_x4(bF, sb + 16384 + off);
#pragma unroll
                for (int mt = 0; mt < 2; mt++)
#pragma unroll
                    for (int hf = 0; hf < 2; hf++)
                        mma_f16(acc[mt][np * 2 + hf], aF[mt], &bF[hf * 2]);
            }
        }
        if (c + 2 < NC) issue(c + 2);
        __syncthreads();
    }

    const int er = lane >> 2;
    const int ec = (lane & 3) * 2;
#pragma unroll
    for (int mt = 0; mt < 2; mt++) {
#pragma unroll
        for (int nt = 0; nt < 8; nt++) {
            int n = colC + warp_n * 64 + nt * 8 + ec;
            float b0 = bias[n], b1 = bias[n + 1];
#pragma unroll
            for (int half = 0; half < 2; half++) {
                int m = rowC + warp_m * 32 + mt * 16 + er + half * 8;
                float v0 = acc[mt][nt][half * 2]     + b0;
                float v1 = acc[mt][nt][half * 2 + 1] + b1;
                size_t o = (size_t)m * N + n;
                if (EPI == 2) {
                    float2 rv = *(const float2*)(R + o);
                    *(float2*)(Cf + o) = make_float2(v0 + rv.x, v1 + rv.y);
                } else {  // gelu -> fp16
                    float g0 = 0.5f * v0 * (1.f + erff(v0 * 0.70710678118654752f));
                    float g1 = 0.5f * v1 * (1.f + erff(v1 * 0.70710678118654752f));
                    __half2 hv = __floats2half2_rn(g0, g1);
                    *(__half2*)(Ch + o) = hv;
                }
            }
        }
    }
}

// ---------------- weight transpose variants -----------------------------------
__global__ __launch_bounds__(256) void transpose_split(const float* __restrict__ W,
                                                       int K, int N,
                                                       __nv_bfloat16* __restrict__ Th,
                                                       __nv_bfloat16* __restrict__ Tl) {
    __shared__ float tile[32][33];
    int n0 = blockIdx.x * 32, k0 = blockIdx.y * 32;
    int tx = threadIdx.x & 31, ty = threadIdx.x >> 5;
#pragma unroll
    for (int i = 0; i < 32; i += 8)
        tile[ty + i][tx] = W[(size_t)(k0 + ty + i) * N + n0 + tx];
    __syncthreads();
#pragma unroll
    for (int i = 0; i < 32; i += 8) {
        float v = tile[tx][ty + i];
        __nv_bfloat16 hi, lo;
        split_bf16(v, hi, lo);
        size_t o = (size_t)(n0 + ty + i) * K + k0 + tx;
        Th[o] = hi;
        Tl[o] = lo;
    }
}

__global__ __launch_bounds__(256) void transpose_f16(const float* __restrict__ W,
                                                     int K, int N,
                                                     __half* __restrict__ Th) {
    __shared__ float tile[32][33];
    int n0 = blockIdx.x * 32, k0 = blockIdx.y * 32;
    int tx = threadIdx.x & 31, ty = threadIdx.x >> 5;
#pragma unroll
    for (int i = 0; i < 32; i += 8)
        tile[ty + i][tx] = W[(size_t)(k0 + ty + i) * N + n0 + tx];
    __syncthreads();
#pragma unroll
    for (int i = 0; i < 32; i += 8) {
        float v = tile[tx][ty + i];
        Th[(size_t)(n0 + ty + i) * K + k0 + tx] = __float2half(v);
    }
}

// ---------------- LayerNorm variants -------------------------------------------
__global__ __launch_bounds__(256) void ln_split(const float* __restrict__ in,
                                                const float* __restrict__ w,
                                                const float* __restrict__ bvec,
                                                __nv_bfloat16* __restrict__ oh,
                                                __nv_bfloat16* __restrict__ ol) {
    int row = blockIdx.x;
    const float* r = in + (size_t)row * C_;
    int tid = threadIdx.x;
    float v[4];
    float s = 0.f, ss = 0.f;
#pragma unroll
    for (int i = 0; i < 4; i++) {
        v[i] = r[tid + i * 256];
        s += v[i];
        ss += v[i] * v[i];
    }
#pragma unroll
    for (int o = 16; o; o >>= 1) {
        s  += __shfl_xor_sync(0xffffffffu, s, o);
        ss += __shfl_xor_sync(0xffffffffu, ss, o);
    }
    __shared__ float rs_[8], rss_[8];
    __shared__ float s_mean, s_rstd;
    int warp = tid >> 5, lane = tid & 31;
    if (lane == 0) { rs_[warp] = s; rss_[warp] = ss; }
    __syncthreads();
    if (tid == 0) {
        float ts = 0.f, tss = 0.f;
#pragma unroll
        for (int i = 0; i < 8; i++) { ts += rs_[i]; tss += rss_[i]; }
        float mean = ts * (1.0f / C_);
        float var = tss * (1.0f / C_) - mean * mean;
        s_mean = mean;
        s_rstd = rsqrtf(var + EPS);
    }
    __syncthreads();
    float mean = s_mean, rstd = s_rstd;
#pragma unroll
    for (int i = 0; i < 4; i++) {
        int c = tid + i * 256;
        float o = (v[i] - mean) * rstd * w[c] + bvec[c];
        __nv_bfloat16 hi, lo;
        split_bf16(o, hi, lo);
        oh[(size_t)row * C_ + c] = hi;
        ol[(size_t)row * C_ + c] = lo;
    }
}

__global__ __launch_bounds__(256) void ln_f16(const float* __restrict__ in,
                                              const float* __restrict__ w,
                                              const float* __restrict__ bvec,
                                              __half* __restrict__ oh) {
    int row = blockIdx.x;
    const float* r = in + (size_t)row * C_;
    int tid = threadIdx.x;
    float v[4];
    float s = 0.f, ss = 0.f;
#pragma unroll
    for (int i = 0; i < 4; i++) {
        v[i] = r[tid + i * 256];
        s += v[i];
        ss += v[i] * v[i];
    }
#pragma unroll
    for (int o = 16; o; o >>= 1) {
        s  += __shfl_xor_sync(0xffffffffu, s, o);
        ss += __shfl_xor_sync(0xffffffffu, ss, o);
    }
    __shared__ float rs_[8], rss_[8];
    __shared__ float s_mean, s_rstd;
    int warp = tid >> 5, lane = tid & 31;
    if (lane == 0) { rs_[warp] = s; rss_[warp] = ss; }
    __syncthreads();
    if (tid == 0) {
        float ts = 0.f, tss = 0.f;
#pragma unroll
        for (int i = 0; i < 8; i++) { ts += rs_[i]; tss += rss_[i]; }
        float mean = ts * (1.0f / C_);
        float var = tss * (1.0f / C_) - mean * mean;
        s_mean = mean;
        s_rstd = rsqrtf(var + EPS);
    }
    __syncthreads();
    float mean = s_mean, rstd = s_rstd;
#pragma unroll
    for (int i = 0; i < 4; i++) {
        int c = tid + i * 256;
        float o = (v[i] - mean) * rstd * w[c] + bvec[c];
        oh[(size_t)row * C_ + c] = __float2half(o);
    }
}

// ---------------- HMMA flash attention (causal, single bf16) -------------------
// smem: Q 16K | 2 x (K 8K | V 8K) = 48KB -> 2 CTAs/SM
constexpr int SMEM_FLASH = 49152;

__global__ __launch_bounds__(256, 2) void flash2() {
    extern __shared__ __align__(1024) char smx[];
    const uint32_t sbase = smem_u32(smx);
    const int tid = threadIdx.x, wid = tid >> 5, lane = tid & 31;
    const int qt = blockIdx.x, bh = blockIdx.y;
    const int q0 = qt * 128;
    const size_t hbase = (size_t)bh * (T_ * HS_);

    {
        const __nv_bfloat16* qh = g_q_hi + hbase + (size_t)q0 * 64;
#pragma unroll
        for (int i = 0; i < 4; i++) {
            int u = tid + 256 * i;
            int r = u >> 3, seg = u & 7;
            uint32_t so = (uint32_t)(r * 128 + ((seg * 16) ^ ((r & 7) * 16)));
            cp_async16(sbase + so, qh + r * 64 + seg * 8);
        }
        cp_commit();
    }

    auto load_kv = [&](int kt) {
        uint32_t sb = sbase + 16384u + (uint32_t)(kt & 1) * 16384u;
        const size_t kb = hbase + (size_t)kt * 64 * 64;
#pragma unroll
        for (int i = 0; i < 2; i++) {
            int u = tid + 256 * i;
            int r = u >> 3, seg = u & 7;
            uint32_t so = (uint32_t)(r * 128 + ((seg * 16) ^ ((r & 7) * 16)));
            size_t go = kb + r * 64 + seg * 8;
            cp_async16(sb + so,        g_k_hi + go);
            cp_async16(sb + 8192 + so, g_v_hi + go);
        }
        cp_commit();
    };

    load_kv(0);
    asm volatile("cp.async.wait_group 1;" ::: "memory");
    __syncthreads();

    uint32_t qh[4][4];
    {
        const int a_mtx = lane >> 3;
        const int a_m = wid * 16 + (a_mtx & 1) * 8 + (lane & 7);
        const int a_kh = (a_mtx >> 1) * 16;
#pragma unroll
        for (int s = 0; s < 4; s++) {
            uint32_t kb = (uint32_t)(s * 32 + a_kh);
            uint32_t off = (uint32_t)(a_m * 128) + (kb ^ (uint32_t)((a_m & 7) * 16));
            ldmatrix_x4(qh[s], sbase + off);
        }
    }

    const int ktmax = qt * 2 + 1;
    float m0 = -1e30f, m1 = -1e30f, l0 = 0.f, l1 = 0.f;
    float acc[8][4];
#pragma unroll
    for (int i = 0; i < 8; i++)
#pragma unroll
        for (int j = 0; j < 4; j++) acc[i][j] = 0.f;

    const int b_mtx = lane >> 3;
    const int kn_in = (b_mtx >> 1) * 8 + (lane & 7);
    const int kk_h = (b_mtx & 1) * 16;
    const int v_row_in = (b_mtx & 1) * 8 + (lane & 7);
    const int v_col = (b_mtx >> 1) * 16;
    const int row0 = q0 + wid * 16 + (lane >> 2);

    for (int kt = 0; kt <= ktmax; kt++) {
        if (kt < ktmax) {
            load_kv(kt + 1);
            asm volatile("cp.async.wait_group 1;" ::: "memory");
        } else {
            asm volatile("cp.async.wait_group 0;" ::: "memory");
        }
        __syncthreads();
        const uint32_t sb = sbase + 16384u + (uint32_t)(kt & 1) * 16384u;

        float S[8][4];
#pragma unroll
        for (int i = 0; i < 8; i++)
#pragma unroll
            for (int j = 0; j < 4; j++) S[i][j] = 0.f;
#pragma unroll
        for (int s = 0; s < 4; s++) {
            uint32_t kf[4][4];
#pragma unroll
            for (int g = 0; g < 4; g++) {
                int n = g * 16 + kn_in;
                uint32_t kb = (uint32_t)(s * 32 + kk_h);
                uint32_t off = (uint32_t)(n * 128) + (kb ^ (uint32_t)((n & 7) * 16));
                ldmatrix_x4(kf[g], sb + off);
            }
#pragma unroll
            for (int nt = 0; nt < 8; nt++)
                mma_bf16(S[nt], qh[s], &kf[nt >> 1][(nt & 1) * 2]);
        }

        if (kt >= 2 * qt) {
#pragma unroll
            for (int nt = 0; nt < 8; nt++) {
                int col = kt * 64 + nt * 8 + (lane & 3) * 2;
                if (col > row0)          S[nt][0] = -1e30f;
                if (col + 1 > row0)      S[nt][1] = -1e30f;
                if (col > row0 + 8)      S[nt][2] = -1e30f;
                if (col + 1 > row0 + 8)  S[nt][3] = -1e30f;
            }
        }

        float mx0 = -1e30f, mx1 = -1e30f;
#pragma unroll
        for (int nt = 0; nt < 8; nt++) {
            mx0 = fmaxf(mx0, fmaxf(S[nt][0], S[nt][1]));
            mx1 = fmaxf(mx1, fmaxf(S[nt][2], S[nt][3]));
        }
        mx0 = fmaxf(mx0, __shfl_xor_sync(0xffffffffu, mx0, 1));
        mx0 = fmaxf(mx0, __shfl_xor_sync(0xffffffffu, mx0, 2));
        mx1 = fmaxf(mx1, __shfl_xor_sync(0xffffffffu, mx1, 1));
        mx1 = fmaxf(mx1, __shfl_xor_sync(0xffffffffu, mx1, 2));
        float mn0 = fmaxf(m0, mx0), mn1 = fmaxf(m1, mx1);
        float al0 = fast_exp(m0 - mn0), al1 = fast_exp(m1 - mn1);
        m0 = mn0; m1 = mn1;
        float sm0 = 0.f, sm1 = 0.f;
#pragma unroll
        for (int nt = 0; nt < 8; nt++) {
            S[nt][0] = fast_exp(S[nt][0] - mn0);
            S[nt][1] = fast_exp(S[nt][1] - mn0);
            S[nt][2] = fast_exp(S[nt][2] - mn1);
            S[nt][3] = fast_exp(S[nt][3] - mn1);
            sm0 += S[nt][0] + S[nt][1];
            sm1 += S[nt][2] + S[nt][3];
        }
        sm0 += __shfl_xor_sync(0xffffffffu, sm0, 1);
        sm0 += __shfl_xor_sync(0xffffffffu, sm0, 2);
        sm1 += __shfl_xor_sync(0xffffffffu, sm1, 1);
        sm1 += __shfl_xor_sync(0xffffffffu, sm1, 2);
        l0 = l0 * al0 + sm0;
        l1 = l1 * al1 + sm1;
#pragma unroll
        for (int nt = 0; nt < 8; nt++) {
            acc[nt][0] *= al0; acc[nt][1] *= al0;
            acc[nt][2] *= al1; acc[nt][3] *= al1;
        }

        uint32_t ph[4][4];
#pragma unroll
        for (int s = 0; s < 4; s++) {
            ph[s][0] = pack2_bf16(S[2 * s][0],     S[2 * s][1]);
            ph[s][1] = pack2_bf16(S[2 * s][2],     S[2 * s][3]);
            ph[s][2] = pack2_bf16(S[2 * s + 1][0], S[2 * s + 1][1]);
            ph[s][3] = pack2_bf16(S[2 * s + 1][2], S[2 * s + 1][3]);
        }

#pragma unroll
        for (int s = 0; s < 4; s++) {
            uint32_t vf[4][4];
#pragma unroll
            for (int g = 0; g < 4; g++) {
                int row = s * 16 + v_row_in;
                uint32_t cb = (uint32_t)(g * 32 + v_col);
                uint32_t off = (uint32_t)(row * 128) + (cb ^ (uint32_t)((row & 7) * 16));
                ldmatrix_x4_trans(vf[g], sb + 8192 + off);
            }
#pragma unroll
            for (int nt = 0; nt < 8; nt++)
                mma_bf16(acc[nt], ph[s], &vf[nt >> 1][(nt & 1) * 2]);
        }
        __syncthreads();
    }

    float inv0 = 1.f / l0, inv1 = 1.f / l1;
    int b = bh >> 4, h = bh & 15;
#pragma unroll
    for (int nt = 0; nt < 8; nt++) {
        int d = nt * 8 + (lane & 3) * 2;
        size_t o0 = (size_t)(b * 2048 + row0) * 1024 + h * 64 + d;
        *(__half2*)(g_y_h + o0) = __floats2half2_rn(acc[nt][0] * inv0, acc[nt][1] * inv0);
        size_t o1 = o0 + 8 * 1024;
        *(__half2*)(g_y_h + o1) = __floats2half2_rn(acc[nt][2] * inv1, acc[nt][3] * inv1);
    }
}

// ---------------- KV quantization ---------------------------------------------
__global__ void init_absmax_kernel() {
    g_absmax[0] = 0u;
    g_absmax[1] = 0u;
}

__global__ __launch_bounds__(256) void absmax_kernel() {
    float mk = 0.f, mv = 0.f;
    int N = BT * C_;
    for (int i = blockIdx.x * blockDim.x + threadIdx.x; i < N;
         i += gridDim.x * blockDim.x) {
        float kk = __bfloat162float(g_k_hi[i]) + __bfloat162float(g_k_lo[i]);
        float vv = __bfloat162float(g_v_hi[i]) + __bfloat162float(g_v_lo[i]);
        mk = fmaxf(mk, fabsf(kk));
        mv = fmaxf(mv, fabsf(vv));
    }
#pragma unroll
    for (int o = 16; o; o >>= 1) {
        mk = fmaxf(mk, __shfl_xor_sync(0xffffffffu, mk, o));
        mv = fmaxf(mv, __shfl_xor_sync(0xffffffffu, mv, o));
    }
    __shared__ float sk_[8], sv_[8];
    int warp = threadIdx.x >> 5, lane = threadIdx.x & 31;
    if (lane == 0) { sk_[warp] = mk; sv_[warp] = mv; }
    __syncthreads();
    if (threadIdx.x == 0) {
        float tk = 0.f, tv = 0.f;
#pragma unroll
        for (int i = 0; i < 8; i++) {
            tk = fmaxf(tk, sk_[i]);
            tv = fmaxf(tv, sv_[i]);
        }
        atomicMax(&g_absmax[0], __float_as_uint(tk));
        atomicMax(&g_absmax[1], __float_as_uint(tv));
    }
}

__global__ __launch_bounds__(256) void quant_kernel(float* __restrict__ out) {
    float ak = __uint_as_float(g_absmax[0]);
    float av = __uint_as_float(g_absmax[1]);
    float sk = ak > 0.f ? ak * (1.f / 127.f) : 1.f;
    float sv = av > 0.f ? av * (1.f / 127.f) : 1.f;
    float rk = 1.f / sk, rv = 1.f / sv;
    int N = BT * C_;
    for (int idx = blockIdx.x * blockDim.x + threadIdx.x; idx < N;
         idx += gridDim.x * blockDim.x) {
        float kk = __bfloat162float(g_k_hi[idx]) + __bfloat162float(g_k_lo[idx]);
        float vv = __bfloat162float(g_v_hi[idx]) + __bfloat162float(g_v_lo[idx]);
        out[OFF_KQ + idx] = fminf(fmaxf(rintf(kk * rk), -127.f), 127.f);
        out[OFF_VQ + idx] = fminf(fmaxf(rintf(vv * rv), -127.f), 127.f);
    }
    if (blockIdx.x == 0 && threadIdx.x == 0) {
        out[OFF_KS] = sk;
        out[OFF_VS] = sv;
    }
}

// ---------------- launch --------------------------------------------------------
extern "C" void kernel_launch(void* const* d_in, const int* in_sizes, int n_in,
                              void* d_out, int out_size) {
    const float* x     = (const float*)d_in[0];
    const float* ln1_w = (const float*)d_in[1];
    const float* ln1_b = (const float*)d_in[2];
    const float* W_qkv = (const float*)d_in[3];
    const float* b_qkv = (const float*)d_in[4];
    const float* W_o   = (const float*)d_in[5];
    const float* b_o   = (const float*)d_in[6];
    const float* ln2_w = (const float*)d_in[7];
    const float* ln2_b = (const float*)d_in[8];
    const float* W_fc  = (const float*)d_in[9];
    const float* b_fc  = (const float*)d_in[10];
    const float* W_pr  = (const float*)d_in[11];
    const float* b_pr  = (const float*)d_in[12];
    float* out = (float*)d_out;

    float *x1;
    __nv_bfloat16 *a_hi, *a_lo, *wqkv_hi, *wqkv_lo;
    __half *y_h, *h2, *fc_h, *wo_h, *wfc_h, *wpr_h;
    cudaGetSymbolAddress((void**)&x1, g_x1);
    cudaGetSymbolAddress((void**)&a_hi, g_a_hi);
    cudaGetSymbolAddress((void**)&a_lo, g_a_lo);
    cudaGetSymbolAddress((void**)&wqkv_hi, g_wqkv_hi);
    cudaGetSymbolAddress((void**)&wqkv_lo, g_wqkv_lo);
    cudaGetSymbolAddress((void**)&y_h, g_y_h);
    cudaGetSymbolAddress((void**)&h2, g_h2);
    cudaGetSymbolAddress((void**)&fc_h, g_fc_h);
    cudaGetSymbolAddress((void**)&wo_h, g_wo_h);
    cudaGetSymbolAddress((void**)&wfc_h, g_wfc_h);
    cudaGetSymbolAddress((void**)&wpr_h, g_wpr_h);

    cudaFuncSetAttribute(flash2,
                         cudaFuncAttributeMaxDynamicSharedMemorySize, SMEM_FLASH);
    cudaFuncSetAttribute(mma_gemm_qkv,
                         cudaFuncAttributeMaxDynamicSharedMemorySize, SMEM_GEMM);
    cudaFuncSetAttribute(mma_gemm_f16<1>,
                         cudaFuncAttributeMaxDynamicSharedMemorySize, SMEM_GEMM_F);
    cudaFuncSetAttribute(mma_gemm_f16<2>,
                         cudaFuncAttributeMaxDynamicSharedMemorySize, SMEM_GEMM_F);

    dim3 tb(256);
    // weight prep
    transpose_split<<<dim3(C3 / 32, C_ / 32), tb>>>(W_qkv, C_, C3, wqkv_hi, wqkv_lo);
    transpose_f16<<<dim3(C_ / 32, C_ / 32), tb>>>(W_o, C_, C_, wo_h);
    transpose_f16<<<dim3(4 * C_ / 32, C_ / 32), tb>>>(W_fc, C_, 4 * C_, wfc_h);
    transpose_f16<<<dim3(C_ / 32, 4 * C_ / 32), tb>>>(W_pr, 4 * C_, C_, wpr_h);

    // 1. LN1 -> bf16 split
    ln_split<<<BT, 256>>>(x, ln1_w, ln1_b, a_hi, a_lo);
    // 2. QKV GEMM -> q single / k,v hi+lo, scatter [B,H,T,HS]
    mma_gemm_qkv<<<dim3(C3 / 128, BT / 128), 256, SMEM_GEMM>>>(
        a_hi, a_lo, wqkv_hi, wqkv_lo, b_qkv, BT, C3, C_);
    // 3. flash attention (single bf16 MMA) -> y fp16
    flash2<<<dim3(T_ / 128, B_ * H_), 256, SMEM_FLASH>>>();
    // 4. proj + residual(x) -> x1 (fp16 GEMM)
    mma_gemm_f16<2><<<dim3(C_ / 128, BT / 128), 256, SMEM_GEMM_F>>>(
        y_h, wo_h, b_o, x, x1, nullptr, BT, C_, C_);
    // 5. LN2 -> fp16
    ln_f16<<<BT, 256>>>(x1, ln2_w, ln2_b, h2);
    // 6. FC + GELU -> fp16 (fp16 GEMM)
    mma_gemm_f16<1><<<dim3(4 * C_ / 128, BT / 128), 256, SMEM_GEMM_F>>>(
        h2, wfc_h, b_fc, nullptr, nullptr, fc_h, BT, 4 * C_, C_);
    // 7. proj + residual(x1) -> out (fp16 GEMM)
    mma_gemm_f16<2><<<dim3(C_ / 128, BT / 128), 256, SMEM_GEMM_F>>>(
        fc_h, wpr_h, b_pr, x1, out + OFF_X, nullptr, BT, C_, 4 * C_);
    // 8-10. KV int8 quantization
    init_absmax_kernel<<<1, 1>>>();
    absmax_kernel<<<2048, 256>>>();
    quant_kernel<<<4096, 256>>>(out);
}